// round 3
// baseline (speedup 1.0000x reference)
#include <cuda_runtime.h>
#include <math.h>

#define Nn   100000
#define Ee   1600000
#define NH   (Nn * 64)

// ---- persistent device scratch (no allocations allowed) ----
__device__ float g_dinv[Nn];
__device__ float g_hb[3][NH];                 // 0: h0, 1/2: ping-pong prop buffers
__device__ float g_seq[(size_t)Nn * 256];     // [N, 4, 64] token sequence
__device__ float g_Mt[4096];   // Mt[b*64+a] = sum_j Wq[j][a]*Wk[j][b]
__device__ float g_Wvo[4096];  // Wvo[b*64+a] = sum_j Wout[a][j]*Wv[j][b]
__device__ float g_p2[64];     // p2[b] = sum_j bq[j]*Wk[j][b]
__device__ float g_bvo[64];    // bvo[a] = sum_j Wout[a][j]*bv[j] + bout[a]

// ================= degree / norm =================
__global__ void k_deg_init() {
    int i = blockIdx.x * blockDim.x + threadIdx.x;
    if (i < Nn) g_dinv[i] = 1.0f;             // self-loop contributes 1
}
__global__ void k_deg_acc(const int* __restrict__ dst) {
    int e = blockIdx.x * blockDim.x + threadIdx.x;
    if (e < Ee) atomicAdd(&g_dinv[dst[e]], 1.0f);
}
__global__ void k_deg_fin() {
    int i = blockIdx.x * blockDim.x + threadIdx.x;
    if (i < Nn) g_dinv[i] = rsqrtf(g_dinv[i]);
}

// ================= h0 = relu(x @ W_in^T + b_in) =================
// 4 rows per warp, float4 weights (padded rows, conflict-free) + float4 x.
__global__ void k_in_linear(const float* __restrict__ x, const float* __restrict__ W,
                            const float* __restrict__ b) {
    extern __shared__ float sm[];
    float* Ws = sm;                 // [64][260]
    float* bb = Ws + 64 * 260;      // 64
    float* xb = bb + 64;            // 8 warps * 1024
    int tid = threadIdx.x;
    for (int i = tid; i < 64 * 64; i += 256) {
        int j = i >> 6, q = i & 63;
        ((float4*)(Ws + j * 260))[q] = ((const float4*)(W + j * 256))[q];
    }
    if (tid < 64) bb[tid] = b[tid];
    __syncthreads();
    int warp = tid >> 5, l = tid & 31;
    float* xw = xb + warp * 1024;
    const float* w0p = Ws + l * 260;
    const float* w1p = Ws + (l + 32) * 260;
    for (int grp = blockIdx.x * 8 + warp; grp < 25000; grp += gridDim.x * 8) {
        int row0 = grp * 4;
        const float4* xg = (const float4*)(x + (size_t)row0 * 256);
        #pragma unroll
        for (int r = 0; r < 4; r++) {
            ((float4*)xw)[r * 64 + l]      = xg[r * 64 + l];
            ((float4*)xw)[r * 64 + l + 32] = xg[r * 64 + l + 32];
        }
        __syncwarp();
        float acc0[4], acc1[4];
        #pragma unroll
        for (int r = 0; r < 4; r++) { acc0[r] = bb[l]; acc1[r] = bb[l + 32]; }
        #pragma unroll 4
        for (int k4 = 0; k4 < 64; k4++) {
            float4 wa = ((const float4*)w0p)[k4];
            float4 wb = ((const float4*)w1p)[k4];
            #pragma unroll
            for (int r = 0; r < 4; r++) {
                float4 xv = ((const float4*)(xw + r * 256))[k4];
                acc0[r] = fmaf(xv.x, wa.x, acc0[r]);
                acc0[r] = fmaf(xv.y, wa.y, acc0[r]);
                acc0[r] = fmaf(xv.z, wa.z, acc0[r]);
                acc0[r] = fmaf(xv.w, wa.w, acc0[r]);
                acc1[r] = fmaf(xv.x, wb.x, acc1[r]);
                acc1[r] = fmaf(xv.y, wb.y, acc1[r]);
                acc1[r] = fmaf(xv.z, wb.z, acc1[r]);
                acc1[r] = fmaf(xv.w, wb.w, acc1[r]);
            }
        }
        #pragma unroll
        for (int r = 0; r < 4; r++) {
            float a0 = fmaxf(acc0[r], 0.f), a1 = fmaxf(acc1[r], 0.f);
            size_t row = row0 + r;
            g_hb[0][row * 64 + l]      = a0;
            g_hb[0][row * 64 + l + 32] = a1;
            g_seq[row * 256 + l]       = a0;
            g_seq[row * 256 + l + 32]  = a1;
        }
        __syncwarp();
    }
}

// ================= propagation (scatter, round-1 proven path) =================
__global__ void k_prop_init(int inb, int outb) {
    int idx = blockIdx.x * blockDim.x + threadIdx.x;     // over NH/4 float4s
    if (idx < NH / 4) {
        float d = g_dinv[idx >> 4];
        float w = d * d;
        float4 v = ((const float4*)g_hb[inb])[idx];
        v.x *= w; v.y *= w; v.z *= w; v.w *= w;
        ((float4*)g_hb[outb])[idx] = v;
    }
}

__global__ void k_prop_edges(const int* __restrict__ src, const int* __restrict__ dst,
                             int inb, int outb) {
    long tid = (long)blockIdx.x * blockDim.x + threadIdx.x;
    int e = (int)(tid >> 4);
    if (e >= Ee) return;
    int q = (int)tid & 15;
    int s = __ldg(src + e), d = __ldg(dst + e);
    float w = g_dinv[s] * g_dinv[d];
    float4 v = ((const float4*)(g_hb[inb] + (size_t)s * 64))[q];
    float* p = g_hb[outb] + (size_t)d * 64 + q * 4;
    asm volatile("red.global.add.v4.f32 [%0], {%1,%2,%3,%4};"
                 :: "l"(p), "f"(v.x * w), "f"(v.y * w), "f"(v.z * w), "f"(v.w * w)
                 : "memory");
}

// ================= token = relu(p @ sg_W[k]^T + sg_b[k]) =================
__global__ void k_tok(int inb, const float* __restrict__ W, const float* __restrict__ b, int slot) {
    __shared__ float Wt[4096];     // Wt[k*64+j] = W[j*64+k]
    __shared__ float bb[64];
    __shared__ float xb[8 * 64];
    int tid = threadIdx.x;
    for (int i = tid; i < 4096; i += 256) {
        int k = i >> 6, j = i & 63;
        Wt[i] = W[j * 64 + k];
    }
    if (tid < 64) bb[tid] = b[tid];
    __syncthreads();
    int warp = tid >> 5, l = tid & 31;
    float* xw = xb + warp * 64;
    const float* pin = g_hb[inb];
    for (int row = blockIdx.x * 8 + warp; row < Nn; row += gridDim.x * 8) {
        xw[l]      = pin[(size_t)row * 64 + l];
        xw[l + 32] = pin[(size_t)row * 64 + l + 32];
        __syncwarp();
        float a0 = bb[l], a1 = bb[l + 32];
        #pragma unroll 8
        for (int k = 0; k < 64; k++) {
            float xk = xw[k];
            a0 = fmaf(xk, Wt[k * 64 + l],      a0);
            a1 = fmaf(xk, Wt[k * 64 + l + 32], a1);
        }
        float* op = g_seq + (size_t)row * 256 + slot * 64;
        op[l]      = fmaxf(a0, 0.f);
        op[l + 32] = fmaxf(a1, 0.f);
        __syncwarp();
    }
}

// ================= precompute folded attention matrices =================
__global__ void k_pre(const float* __restrict__ inW, const float* __restrict__ inb,
                      const float* __restrict__ WoutG, const float* __restrict__ boutG) {
    int e = blockIdx.x * blockDim.x + threadIdx.x;
    if (e < 4096) {
        int bcol = e >> 6, a = e & 63;
        float m = 0.f, wv = 0.f;
        for (int j = 0; j < 64; j++) {
            m  = fmaf(__ldg(inW + j * 64 + a),   __ldg(inW + (64 + j) * 64 + bcol), m);
            wv = fmaf(__ldg(WoutG + a * 64 + j), __ldg(inW + (128 + j) * 64 + bcol), wv);
        }
        g_Mt[e] = m;
        g_Wvo[e] = wv;
    }
    if (e < 64) {
        float p = 0.f;
        for (int j = 0; j < 64; j++) p = fmaf(__ldg(inb + j), __ldg(inW + (64 + j) * 64 + e), p);
        g_p2[e] = p;
    } else if (e < 128) {
        int a = e - 64;
        float bv = __ldg(boutG + a);
        for (int j = 0; j < 64; j++) bv = fmaf(__ldg(WoutG + a * 64 + j), __ldg(inb + 128 + j), bv);
        g_bvo[a] = bv;
    }
}

// ================= fused transformer + mean + classifier =================
// 16 warps/CTA, 1 warp per node. Lane: t = l>>3 (token), g = l&7.
__global__ void __launch_bounds__(512, 1) k_former(
    const float* __restrict__ W1_g, const float* __restrict__ b1_g,
    const float* __restrict__ W2_g, const float* __restrict__ b2_g,
    const float* __restrict__ ln1w_g, const float* __restrict__ ln1b_g,
    const float* __restrict__ ln2w_g, const float* __restrict__ ln2b_g,
    const float* __restrict__ Wcls_g, const float* __restrict__ bcls_g,
    float* __restrict__ out)
{
    extern __shared__ float sm[];
    float* MtS   = sm;              // [64][68]
    float* WvoS  = MtS + 4352;      // [64][68]
    float* W1S   = WvoS + 4352;     // [64][132]
    float* W2S   = W1S + 8448;      // [128][68]
    float* WclsS = W2S + 8704;      // [64][40]
    float* p2S   = WclsS + 2560;
    float* bvoS  = p2S + 64;
    float* b1S   = bvoS + 64;
    float* b2S   = b1S + 128;
    float* bclsS = b2S + 64;
    float* ln1wS = bclsS + 40;
    float* ln1bS = ln1wS + 64;
    float* ln2wS = ln1bS + 64;
    float* ln2bS = ln2wS + 64;
    float* scratch = ln2bS + 64;    // 16 warps * 1104

    int tid = threadIdx.x;
    for (int i = tid; i < 4096; i += 512) {
        int bc = i >> 6, a = i & 63;
        MtS[bc * 68 + a]  = g_Mt[i];
        WvoS[bc * 68 + a] = g_Wvo[i];
    }
    for (int i = tid; i < 8192; i += 512) { int j = i & 127, k = i >> 7; W1S[k * 132 + j] = W1_g[j * 64 + k]; }
    for (int i = tid; i < 8192; i += 512) { int j = i & 63,  k = i >> 6; W2S[k * 68 + j]  = W2_g[j * 128 + k]; }
    for (int i = tid; i < 2560; i += 512) { int j = i % 40,  k = i / 40; WclsS[k * 40 + j] = Wcls_g[j * 64 + k]; }
    if (tid < 64) {
        p2S[tid] = g_p2[tid]; bvoS[tid] = g_bvo[tid]; b2S[tid] = b2_g[tid];
        ln1wS[tid] = ln1w_g[tid]; ln1bS[tid] = ln1b_g[tid];
        ln2wS[tid] = ln2w_g[tid]; ln2bS[tid] = ln2b_g[tid];
    }
    if (tid < 128) b1S[tid] = b1_g[tid];
    if (tid < 40) bclsS[tid] = bcls_g[tid];
    __syncthreads();

    int warp = tid >> 5, l = tid & 31;
    float* s   = scratch + warp * 1104;  // 256
    float* z   = s + 256;                // 256
    float* b2f = z + 256;                // 512
    float* sc  = b2f + 512;              // 16
    float* hb  = sc + 16;                // 64
    const int t = l >> 3, g = l & 7;
    float* srow = s + t * 64;

    for (int n = blockIdx.x * 16 + warp; n < Nn; n += gridDim.x * 16) {
        const float4* sp = (const float4*)(g_seq + (size_t)n * 256);
        ((float4*)s)[l]      = sp[l];
        ((float4*)s)[l + 32] = sp[l + 32];
        __syncwarp();

        // ---- z_t = M seq_t ----
        {
            float acc[8];
            #pragma unroll
            for (int i = 0; i < 8; i++) acc[i] = 0.f;
            for (int k4 = 0; k4 < 16; k4++) {
                float4 xv = ((const float4*)srow)[k4];
                #pragma unroll
                for (int kk = 0; kk < 4; kk++) {
                    const float4* wr = (const float4*)(MtS + (k4 * 4 + kk) * 68 + g * 8);
                    float4 wA = wr[0], wB = wr[1];
                    float xk = kk == 0 ? xv.x : kk == 1 ? xv.y : kk == 2 ? xv.z : xv.w;
                    acc[0] = fmaf(xk, wA.x, acc[0]); acc[1] = fmaf(xk, wA.y, acc[1]);
                    acc[2] = fmaf(xk, wA.z, acc[2]); acc[3] = fmaf(xk, wA.w, acc[3]);
                    acc[4] = fmaf(xk, wB.x, acc[4]); acc[5] = fmaf(xk, wB.y, acc[5]);
                    acc[6] = fmaf(xk, wB.z, acc[6]); acc[7] = fmaf(xk, wB.w, acc[7]);
                }
            }
            float* zp = z + t * 64 + g * 8;
            ((float4*)zp)[0] = make_float4(acc[0], acc[1], acc[2], acc[3]);
            ((float4*)zp)[1] = make_float4(acc[4], acc[5], acc[6], acc[7]);
        }
        __syncwarp();

        // ---- scores + softmax ----
        if (l < 16) {
            int ss = l >> 2, tt = l & 3;
            const float4* ap = (const float4*)(s + ss * 64);
            const float4* zp = (const float4*)(z + tt * 64);
            const float4* bp = (const float4*)(s + tt * 64);
            const float4* pp = (const float4*)p2S;
            float d = 0.f;
            #pragma unroll 4
            for (int k4 = 0; k4 < 16; k4++) {
                float4 a = ap[k4], zz = zp[k4], bq = bp[k4], p = pp[k4];
                d += a.x * zz.x + a.y * zz.y + a.z * zz.z + a.w * zz.w;
                d += p.x * bq.x + p.y * bq.y + p.z * bq.z + p.w * bq.w;
            }
            sc[l] = d * 0.125f;
        }
        __syncwarp();
        if (l < 4) {
            float s0 = sc[l*4], s1 = sc[l*4+1], s2 = sc[l*4+2], s3 = sc[l*4+3];
            float m = fmaxf(fmaxf(s0, s1), fmaxf(s2, s3));
            float e0 = __expf(s0 - m), e1 = __expf(s1 - m), e2 = __expf(s2 - m), e3 = __expf(s3 - m);
            float inv = 1.f / (e0 + e1 + e2 + e3);
            sc[l*4] = e0*inv; sc[l*4+1] = e1*inv; sc[l*4+2] = e2*inv; sc[l*4+3] = e3*inv;
        }
        __syncwarp();

        // ---- m_t = sum_c P[t,c] seq_c ----
        {
            float w0 = sc[t*4], w1 = sc[t*4+1], w2 = sc[t*4+2], w3 = sc[t*4+3];
            #pragma unroll
            for (int c = 0; c < 2; c++) {
                int q = g * 2 + c;
                float4 s0 = ((const float4*)s)[q];
                float4 s1 = ((const float4*)(s + 64))[q];
                float4 s2 = ((const float4*)(s + 128))[q];
                float4 s3 = ((const float4*)(s + 192))[q];
                float4 r;
                r.x = w0*s0.x + w1*s1.x + w2*s2.x + w3*s3.x;
                r.y = w0*s0.y + w1*s1.y + w2*s2.y + w3*s3.y;
                r.z = w0*s0.z + w1*s1.z + w2*s2.z + w3*s3.z;
                r.w = w0*s0.w + w1*s1.w + w2*s2.w + w3*s3.w;
                ((float4*)(b2f + t * 64))[q] = r;
            }
        }
        __syncwarp();

        // ---- out = Wvo m + bvo, residual, LN1 ----
        {
            float r[8];
            #pragma unroll
            for (int i = 0; i < 8; i++) r[i] = bvoS[g * 8 + i];
            const float* arow = b2f + t * 64;
            for (int k4 = 0; k4 < 16; k4++) {
                float4 av = ((const float4*)arow)[k4];
                #pragma unroll
                for (int kk = 0; kk < 4; kk++) {
                    const float4* wr = (const float4*)(WvoS + (k4 * 4 + kk) * 68 + g * 8);
                    float4 wA = wr[0], wB = wr[1];
                    float ak = kk == 0 ? av.x : kk == 1 ? av.y : kk == 2 ? av.z : av.w;
                    r[0] = fmaf(ak, wA.x, r[0]); r[1] = fmaf(ak, wA.y, r[1]);
                    r[2] = fmaf(ak, wA.z, r[2]); r[3] = fmaf(ak, wA.w, r[3]);
                    r[4] = fmaf(ak, wB.x, r[4]); r[5] = fmaf(ak, wB.y, r[5]);
                    r[6] = fmaf(ak, wB.z, r[6]); r[7] = fmaf(ak, wB.w, r[7]);
                }
            }
            float4 rs0 = ((const float4*)srow)[g*2], rs1 = ((const float4*)srow)[g*2+1];
            r[0] += rs0.x; r[1] += rs0.y; r[2] += rs0.z; r[3] += rs0.w;
            r[4] += rs1.x; r[5] += rs1.y; r[6] += rs1.z; r[7] += rs1.w;
            float sum = 0.f;
            #pragma unroll
            for (int i = 0; i < 8; i++) sum += r[i];
            sum += __shfl_xor_sync(0xffffffffu, sum, 1);
            sum += __shfl_xor_sync(0xffffffffu, sum, 2);
            sum += __shfl_xor_sync(0xffffffffu, sum, 4);
            float mean = sum * 0.015625f;
            float sq = 0.f;
            #pragma unroll
            for (int i = 0; i < 8; i++) { float dd = r[i] - mean; sq = fmaf(dd, dd, sq); }
            sq += __shfl_xor_sync(0xffffffffu, sq, 1);
            sq += __shfl_xor_sync(0xffffffffu, sq, 2);
            sq += __shfl_xor_sync(0xffffffffu, sq, 4);
            float inv = rsqrtf(sq * 0.015625f + 1e-5f);
            float4 w0v = ((const float4*)ln1wS)[g*2], w1v = ((const float4*)ln1wS)[g*2+1];
            float4 b0v = ((const float4*)ln1bS)[g*2], b1v = ((const float4*)ln1bS)[g*2+1];
            float4 o0, o1;
            o0.x = (r[0]-mean)*inv*w0v.x + b0v.x; o0.y = (r[1]-mean)*inv*w0v.y + b0v.y;
            o0.z = (r[2]-mean)*inv*w0v.z + b0v.z; o0.w = (r[3]-mean)*inv*w0v.w + b0v.w;
            o1.x = (r[4]-mean)*inv*w1v.x + b1v.x; o1.y = (r[5]-mean)*inv*w1v.y + b1v.y;
            o1.z = (r[6]-mean)*inv*w1v.z + b1v.z; o1.w = (r[7]-mean)*inv*w1v.w + b1v.w;
            ((float4*)srow)[g*2] = o0; ((float4*)srow)[g*2+1] = o1;
        }
        __syncwarp();

        // ---- FF1 + exact gelu ----
        {
            float ga[16];
            #pragma unroll
            for (int i = 0; i < 16; i++) ga[i] = b1S[g * 16 + i];
            for (int k4 = 0; k4 < 16; k4++) {
                float4 xv = ((const float4*)srow)[k4];
                #pragma unroll
                for (int kk = 0; kk < 4; kk++) {
                    const float4* wr = (const float4*)(W1S + (k4 * 4 + kk) * 132 + g * 16);
                    float4 wA = wr[0], wB = wr[1], wC = wr[2], wD = wr[3];
                    float xk = kk == 0 ? xv.x : kk == 1 ? xv.y : kk == 2 ? xv.z : xv.w;
                    ga[0]  = fmaf(xk, wA.x, ga[0]);  ga[1]  = fmaf(xk, wA.y, ga[1]);
                    ga[2]  = fmaf(xk, wA.z, ga[2]);  ga[3]  = fmaf(xk, wA.w, ga[3]);
                    ga[4]  = fmaf(xk, wB.x, ga[4]);  ga[5]  = fmaf(xk, wB.y, ga[5]);
                    ga[6]  = fmaf(xk, wB.z, ga[6]);  ga[7]  = fmaf(xk, wB.w, ga[7]);
                    ga[8]  = fmaf(xk, wC.x, ga[8]);  ga[9]  = fmaf(xk, wC.y, ga[9]);
                    ga[10] = fmaf(xk, wC.z, ga[10]); ga[11] = fmaf(xk, wC.w, ga[11]);
                    ga[12] = fmaf(xk, wD.x, ga[12]); ga[13] = fmaf(xk, wD.y, ga[13]);
                    ga[14] = fmaf(xk, wD.z, ga[14]); ga[15] = fmaf(xk, wD.w, ga[15]);
                }
            }
            #pragma unroll
            for (int i = 0; i < 16; i++) {
                float xg = ga[i];
                ga[i] = 0.5f * xg * (1.0f + erff(xg * 0.70710678118f));
            }
            float* gp = b2f + t * 128 + g * 16;
            ((float4*)gp)[0] = make_float4(ga[0], ga[1], ga[2], ga[3]);
            ((float4*)gp)[1] = make_float4(ga[4], ga[5], ga[6], ga[7]);
            ((float4*)gp)[2] = make_float4(ga[8], ga[9], ga[10], ga[11]);
            ((float4*)gp)[3] = make_float4(ga[12], ga[13], ga[14], ga[15]);
        }
        __syncwarp();

        // ---- FF2 + residual + LN2 + token mean ----
        {
            float f[8];
            #pragma unroll
            for (int i = 0; i < 8; i++) f[i] = b2S[g * 8 + i];
            const float* grow = b2f + t * 128;
            for (int k4 = 0; k4 < 32; k4++) {
                float4 gv = ((const float4*)grow)[k4];
                #pragma unroll
                for (int kk = 0; kk < 4; kk++) {
                    const float4* wr = (const float4*)(W2S + (k4 * 4 + kk) * 68 + g * 8);
                    float4 wA = wr[0], wB = wr[1];
                    float gk = kk == 0 ? gv.x : kk == 1 ? gv.y : kk == 2 ? gv.z : gv.w;
                    f[0] = fmaf(gk, wA.x, f[0]); f[1] = fmaf(gk, wA.y, f[1]);
                    f[2] = fmaf(gk, wA.z, f[2]); f[3] = fmaf(gk, wA.w, f[3]);
                    f[4] = fmaf(gk, wB.x, f[4]); f[5] = fmaf(gk, wB.y, f[5]);
                    f[6] = fmaf(gk, wB.z, f[6]); f[7] = fmaf(gk, wB.w, f[7]);
                }
            }
            float4 rs0 = ((const float4*)srow)[g*2], rs1 = ((const float4*)srow)[g*2+1];
            f[0] += rs0.x; f[1] += rs0.y; f[2] += rs0.z; f[3] += rs0.w;
            f[4] += rs1.x; f[5] += rs1.y; f[6] += rs1.z; f[7] += rs1.w;
            float sum = 0.f;
            #pragma unroll
            for (int i = 0; i < 8; i++) sum += f[i];
            sum += __shfl_xor_sync(0xffffffffu, sum, 1);
            sum += __shfl_xor_sync(0xffffffffu, sum, 2);
            sum += __shfl_xor_sync(0xffffffffu, sum, 4);
            float mean = sum * 0.015625f;
            float sq = 0.f;
            #pragma unroll
            for (int i = 0; i < 8; i++) { float dd = f[i] - mean; sq = fmaf(dd, dd, sq); }
            sq += __shfl_xor_sync(0xffffffffu, sq, 1);
            sq += __shfl_xor_sync(0xffffffffu, sq, 2);
            sq += __shfl_xor_sync(0xffffffffu, sq, 4);
            float inv = rsqrtf(sq * 0.015625f + 1e-5f);
            #pragma unroll
            for (int i = 0; i < 8; i++) {
                int j = g * 8 + i;
                float x2 = (f[i] - mean) * inv * ln2wS[j] + ln2bS[j];
                x2 += __shfl_xor_sync(0xffffffffu, x2, 8);
                x2 += __shfl_xor_sync(0xffffffffu, x2, 16);
                if (t == 0) hb[j] = x2 * 0.25f;
            }
        }
        __syncwarp();

        // ---- classifier ----
        {
            float o0 = bclsS[l];
            float o1 = bclsS[32 + (l & 7)];
            #pragma unroll 4
            for (int k4 = 0; k4 < 16; k4++) {
                float4 hv = ((const float4*)hb)[k4];
                const float* wr = WclsS + k4 * 160;
                o0 = fmaf(hv.x, wr[l], o0);        o1 = fmaf(hv.x, wr[32 + (l & 7)], o1);
                o0 = fmaf(hv.y, wr[40 + l], o0);   o1 = fmaf(hv.y, wr[72 + (l & 7)], o1);
                o0 = fmaf(hv.z, wr[80 + l], o0);   o1 = fmaf(hv.z, wr[112 + (l & 7)], o1);
                o0 = fmaf(hv.w, wr[120 + l], o0);  o1 = fmaf(hv.w, wr[152 + (l & 7)], o1);
            }
            out[(size_t)n * 40 + l] = o0;
            if (l < 8) out[(size_t)n * 40 + 32 + l] = o1;
        }
        __syncwarp();
    }
}

extern "C" void kernel_launch(void* const* d_in, const int* in_sizes, int n_in,
                              void* d_out, int out_size) {
    const float* x     = (const float*)d_in[0];
    const int*   ei    = (const int*)d_in[1];
    const float* W_in  = (const float*)d_in[2];
    const float* b_in  = (const float*)d_in[3];
    const float* sg_W  = (const float*)d_in[4];
    const float* sg_b  = (const float*)d_in[5];
    const float* inW   = (const float*)d_in[6];
    const float* inb   = (const float*)d_in[7];
    const float* Wout  = (const float*)d_in[8];
    const float* bout  = (const float*)d_in[9];
    const float* W1    = (const float*)d_in[10];
    const float* b1    = (const float*)d_in[11];
    const float* W2    = (const float*)d_in[12];
    const float* b2    = (const float*)d_in[13];
    const float* ln1w  = (const float*)d_in[14];
    const float* ln1b  = (const float*)d_in[15];
    const float* ln2w  = (const float*)d_in[16];
    const float* ln2b  = (const float*)d_in[17];
    const float* Wcls  = (const float*)d_in[18];
    const float* bcls  = (const float*)d_in[19];
    float* out = (float*)d_out;

    cudaFuncSetAttribute(k_in_linear, cudaFuncAttributeMaxDynamicSharedMemorySize, 99584);
    cudaFuncSetAttribute(k_former,    cudaFuncAttributeMaxDynamicSharedMemorySize, 186784);

    // degree / dinv
    k_deg_init<<<(Nn + 255) / 256, 256>>>();
    k_deg_acc<<<(Ee + 255) / 256, 256>>>(ei + Ee);
    k_deg_fin<<<(Nn + 255) / 256, 256>>>();

    // h0 + seq slot 0
    k_in_linear<<<592, 256, 99584>>>(x, W_in, b_in);

    // folded attention matrices
    k_pre<<<16, 256>>>(inW, inb, Wout, bout);

    // 3 hops: buffers 0 -> 1 -> 2 -> 1 (scatter + RED, proven fast path)
    const int inb_[3]  = {0, 1, 2};
    const int outb_[3] = {1, 2, 1};
    for (int hop = 0; hop < 3; hop++) {
        k_prop_init<<<(NH / 4 + 255) / 256, 256>>>(inb_[hop], outb_[hop]);
        k_prop_edges<<<(Ee * 16) / 256, 256>>>(ei, ei + Ee, inb_[hop], outb_[hop]);
        k_tok<<<1024, 256>>>(outb_[hop], sg_W + hop * 4096, sg_b + hop * 64, hop + 1);
    }

    // fused transformer + pooling + classifier
    k_former<<<148, 512, 186784>>>(W1, b1, W2, b2, ln1w, ln1b, ln2w, ln2b, Wcls, bcls, out);
}

// round 4
// speedup vs baseline: 1.5143x; 1.5143x over previous
#include <cuda_runtime.h>
#include <math.h>

#define Nn   100000
#define Ee   1600000
#define INC  256
#define NH   (Nn * 64)

// Scratch (static device globals; no allocations allowed)
__device__ float g_dinv[Nn];
__device__ float g_hb[3][NH];          // 0: h0, 1/2: ping-pong propagation buffers
__device__ float g_seq[(size_t)Nn * 256];  // [N, 4, 64] token sequence

// ---------------- degree / norm ----------------
__global__ void k_deg_init() {
    int i = blockIdx.x * blockDim.x + threadIdx.x;
    if (i < Nn) g_dinv[i] = 1.0f;           // self-loop contributes 1
}
__global__ void k_deg_acc(const int* __restrict__ dst) {
    int e = blockIdx.x * blockDim.x + threadIdx.x;
    if (e < Ee) atomicAdd(&g_dinv[dst[e]], 1.0f);
}
__global__ void k_deg_fin() {
    int i = blockIdx.x * blockDim.x + threadIdx.x;
    if (i < Nn) g_dinv[i] = rsqrtf(g_dinv[i]);
}

// ---------------- h0 = relu(x @ W_in^T + b_in) (fast round-3 version) ----------------
__global__ void k_in_linear(const float* __restrict__ x, const float* __restrict__ W,
                            const float* __restrict__ b) {
    extern __shared__ float sm[];
    float* Ws = sm;                 // [64][260]
    float* bb = Ws + 64 * 260;      // 64
    float* xb = bb + 64;            // 8 warps * 1024
    int tid = threadIdx.x;
    for (int i = tid; i < 64 * 64; i += 256) {
        int j = i >> 6, q = i & 63;
        ((float4*)(Ws + j * 260))[q] = ((const float4*)(W + j * 256))[q];
    }
    if (tid < 64) bb[tid] = b[tid];
    __syncthreads();
    int warp = tid >> 5, l = tid & 31;
    float* xw = xb + warp * 1024;
    const float* w0p = Ws + l * 260;
    const float* w1p = Ws + (l + 32) * 260;
    for (int grp = blockIdx.x * 8 + warp; grp < 25000; grp += gridDim.x * 8) {
        int row0 = grp * 4;
        const float4* xg = (const float4*)(x + (size_t)row0 * 256);
        #pragma unroll
        for (int r = 0; r < 4; r++) {
            ((float4*)xw)[r * 64 + l]      = xg[r * 64 + l];
            ((float4*)xw)[r * 64 + l + 32] = xg[r * 64 + l + 32];
        }
        __syncwarp();
        float acc0[4], acc1[4];
        #pragma unroll
        for (int r = 0; r < 4; r++) { acc0[r] = bb[l]; acc1[r] = bb[l + 32]; }
        #pragma unroll 4
        for (int k4 = 0; k4 < 64; k4++) {
            float4 wa = ((const float4*)w0p)[k4];
            float4 wb = ((const float4*)w1p)[k4];
            #pragma unroll
            for (int r = 0; r < 4; r++) {
                float4 xv = ((const float4*)(xw + r * 256))[k4];
                acc0[r] = fmaf(xv.x, wa.x, acc0[r]);
                acc0[r] = fmaf(xv.y, wa.y, acc0[r]);
                acc0[r] = fmaf(xv.z, wa.z, acc0[r]);
                acc0[r] = fmaf(xv.w, wa.w, acc0[r]);
                acc1[r] = fmaf(xv.x, wb.x, acc1[r]);
                acc1[r] = fmaf(xv.y, wb.y, acc1[r]);
                acc1[r] = fmaf(xv.z, wb.z, acc1[r]);
                acc1[r] = fmaf(xv.w, wb.w, acc1[r]);
            }
        }
        #pragma unroll
        for (int r = 0; r < 4; r++) {
            float a0 = fmaxf(acc0[r], 0.f), a1 = fmaxf(acc1[r], 0.f);
            size_t row = row0 + r;
            g_hb[0][row * 64 + l]      = a0;
            g_hb[0][row * 64 + l + 32] = a1;
            g_seq[row * 256 + l]       = a0;
            g_seq[row * 256 + l + 32]  = a1;
        }
        __syncwarp();
    }
}

// ---------------- propagation: out = dinv^2 * in (self loop) then scatter edges ----------------
__global__ void k_prop_init(int inb, int outb) {
    int idx = blockIdx.x * blockDim.x + threadIdx.x;     // over NH/4 float4s
    if (idx < NH / 4) {
        float d = g_dinv[idx >> 4];
        float w = d * d;
        float4 v = ((const float4*)g_hb[inb])[idx];
        v.x *= w; v.y *= w; v.z *= w; v.w *= w;
        ((float4*)g_hb[outb])[idx] = v;
    }
}

__global__ void k_prop_edges(const int* __restrict__ src, const int* __restrict__ dst,
                             int inb, int outb) {
    long tid = (long)blockIdx.x * blockDim.x + threadIdx.x;
    int e = (int)(tid >> 4);
    if (e >= Ee) return;
    int q = (int)tid & 15;
    int s = __ldg(src + e), d = __ldg(dst + e);
    float w = g_dinv[s] * g_dinv[d];
    float4 v = ((const float4*)(g_hb[inb] + (size_t)s * 64))[q];
    float* p = g_hb[outb] + (size_t)d * 64 + q * 4;
    asm volatile("red.global.add.v4.f32 [%0], {%1,%2,%3,%4};"
                 :: "l"(p), "f"(v.x * w), "f"(v.y * w), "f"(v.z * w), "f"(v.w * w)
                 : "memory");
}

// ---------------- token = relu(p @ sg_W[k]^T + sg_b[k]) into seq slot ----------------
__global__ void k_tok(int inb, const float* __restrict__ W, const float* __restrict__ b, int slot) {
    __shared__ float Wt[4096];     // [64][64] transposed
    __shared__ float bb[64];
    __shared__ float xb[8 * 64];
    int tid = threadIdx.x;
    for (int i = tid; i < 4096; i += 256) {
        int k = i >> 6, j = i & 63;
        Wt[i] = W[j * 64 + k];
    }
    if (tid < 64) bb[tid] = b[tid];
    __syncthreads();
    int warp = tid >> 5, l = tid & 31;
    float* xw = xb + warp * 64;
    const float* pin = g_hb[inb];
    for (int row = blockIdx.x * 8 + warp; row < Nn; row += gridDim.x * 8) {
        xw[l]      = pin[(size_t)row * 64 + l];
        xw[l + 32] = pin[(size_t)row * 64 + l + 32];
        __syncwarp();
        float a0 = bb[l], a1 = bb[l + 32];
        #pragma unroll 8
        for (int k = 0; k < 64; k++) {
            float xk = xw[k];
            a0 = fmaf(xk, Wt[k * 64 + l],      a0);
            a1 = fmaf(xk, Wt[k * 64 + l + 32], a1);
        }
        float* op = g_seq + (size_t)row * 256 + slot * 64;
        op[l]      = fmaxf(a0, 0.f);
        op[l + 32] = fmaxf(a1, 0.f);
        __syncwarp();
    }
}

// ---------------- fused transformer layer + mean + classifier (round-1 proven) ----------------
// One warp per node. Lane layout: t = l>>3 (token 0..3), g = l&7 (8 lanes per token).
__global__ void __launch_bounds__(256, 1) k_former(
    const float* __restrict__ Wqkv_g, const float* __restrict__ bqkv_g,
    const float* __restrict__ Wout_g, const float* __restrict__ bout_g,
    const float* __restrict__ W1_g,   const float* __restrict__ b1_g,
    const float* __restrict__ W2_g,   const float* __restrict__ b2_g,
    const float* __restrict__ ln1w_g, const float* __restrict__ ln1b_g,
    const float* __restrict__ ln2w_g, const float* __restrict__ ln2b_g,
    const float* __restrict__ Wcls_g, const float* __restrict__ bcls_g,
    float* __restrict__ out)
{
    extern __shared__ float sm[];
    float* Wqkv = sm;             // 64*192, Wqkv[k*192+j] = Wqkv_g[j*64+k]
    float* Wout = Wqkv + 12288;   // 64*64
    float* W1   = Wout + 4096;    // 64*128
    float* W2   = W1 + 8192;      // 128*64
    float* Wcls = W2 + 8192;      // 64*40
    float* bqkv = Wcls + 2560;    // 192
    float* bout = bqkv + 192;     // 64
    float* b1   = bout + 64;      // 128
    float* b2   = b1 + 128;       // 64
    float* bcls = b2 + 64;        // 40
    float* ln1w = bcls + 40;      // 64
    float* ln1b = ln1w + 64;
    float* ln2w = ln1b + 64;
    float* ln2b = ln2w + 64;
    float* wbuf = ln2b + 64;      // per-warp scratch: 8 * 1616

    int tid = threadIdx.x;
    for (int i = tid; i < 12288; i += 256) { int k = i / 192, j = i % 192; Wqkv[i] = Wqkv_g[j * 64 + k]; }
    for (int i = tid; i < 4096;  i += 256) { int k = i >> 6,  j = i & 63;  Wout[i] = Wout_g[j * 64 + k]; }
    for (int i = tid; i < 8192;  i += 256) { int k = i >> 7,  j = i & 127; W1[i]   = W1_g[j * 64 + k]; }
    for (int i = tid; i < 8192;  i += 256) { int k = i >> 6,  j = i & 63;  W2[i]   = W2_g[j * 128 + k]; }
    for (int i = tid; i < 2560;  i += 256) { int k = i / 40,  j = i % 40;  Wcls[i] = Wcls_g[j * 64 + k]; }
    if (tid < 192) bqkv[tid] = bqkv_g[tid];
    if (tid < 128) b1[tid]   = b1_g[tid];
    if (tid < 64) {
        bout[tid] = bout_g[tid]; b2[tid] = b2_g[tid];
        ln1w[tid] = ln1w_g[tid]; ln1b[tid] = ln1b_g[tid];
        ln2w[tid] = ln2w_g[tid]; ln2b[tid] = ln2b_g[tid];
    }
    if (tid < 40) bcls[tid] = bcls_g[tid];
    __syncthreads();

    int warp = tid >> 5, l = tid & 31;
    float* s   = wbuf + warp * 1616;   // 256: seq tile / x1 / x2 residual chain
    float* q3  = s + 256;              // 768: qkv
    float* b2f = q3 + 768;             // 512: attn-out then gelu activations
    float* sc  = b2f + 512;            // 16: scores
    float* hb  = sc + 16;              // 64: pooled features
    const int t = l >> 3, g = l & 7;
    const float* srow = s + t * 64;
    float* srw = s + t * 64;

    for (int n = blockIdx.x * 8 + warp; n < Nn; n += gridDim.x * 8) {
        const float4* sp = (const float4*)(g_seq + (size_t)n * 256);
        ((float4*)s)[l]      = sp[l];
        ((float4*)s)[l + 32] = sp[l + 32];
        __syncwarp();

        // ---- QKV: lane computes 24 outputs j = g + 8i for its token ----
        float acc[24];
        #pragma unroll
        for (int i = 0; i < 24; i++) acc[i] = bqkv[g + 8 * i];
        for (int k = 0; k < 64; k++) {
            float sk = srow[k];
            const float* wr = Wqkv + k * 192 + g;
            #pragma unroll
            for (int i = 0; i < 24; i++) acc[i] = fmaf(sk, wr[8 * i], acc[i]);
        }
        #pragma unroll
        for (int i = 0; i < 24; i++) q3[t * 192 + g + 8 * i] = acc[i];
        __syncwarp();

        // ---- scores (4x4) + softmax ----
        if (l < 16) {
            const float* qp = q3 + (l >> 2) * 192;
            const float* kp = q3 + (l & 3) * 192 + 64;
            float d = 0.f;
            #pragma unroll
            for (int k = 0; k < 64; k++) d = fmaf(qp[k], kp[k], d);
            sc[l] = d * 0.125f;
        }
        __syncwarp();
        if (l < 4) {
            float s0 = sc[l*4], s1 = sc[l*4+1], s2 = sc[l*4+2], s3 = sc[l*4+3];
            float m = fmaxf(fmaxf(s0, s1), fmaxf(s2, s3));
            float e0 = __expf(s0 - m), e1 = __expf(s1 - m), e2 = __expf(s2 - m), e3 = __expf(s3 - m);
            float inv = 1.f / (e0 + e1 + e2 + e3);
            sc[l*4] = e0*inv; sc[l*4+1] = e1*inv; sc[l*4+2] = e2*inv; sc[l*4+3] = e3*inv;
        }
        __syncwarp();

        // ---- attn @ V ----
        {
            float w0 = sc[t*4+0], w1 = sc[t*4+1], w2 = sc[t*4+2], w3 = sc[t*4+3];
            #pragma unroll
            for (int i = 0; i < 8; i++) {
                int h = g + 8 * i;
                float v = w0 * q3[128 + h] + w1 * q3[320 + h] + w2 * q3[512 + h] + w3 * q3[704 + h];
                b2f[t * 64 + h] = v;
            }
        }
        __syncwarp();

        // ---- out proj + residual + LN1 (overwrite s with x1) ----
        {
            float r[8];
            #pragma unroll
            for (int i = 0; i < 8; i++) r[i] = bout[g + 8 * i];
            const float* arow = b2f + t * 64;
            for (int k = 0; k < 64; k++) {
                float ak = arow[k];
                const float* wr = Wout + k * 64 + g;
                #pragma unroll
                for (int i = 0; i < 8; i++) r[i] = fmaf(ak, wr[8 * i], r[i]);
            }
            float sum = 0.f;
            #pragma unroll
            for (int i = 0; i < 8; i++) { r[i] += srow[g + 8 * i]; sum += r[i]; }
            sum += __shfl_xor_sync(0xffffffffu, sum, 1);
            sum += __shfl_xor_sync(0xffffffffu, sum, 2);
            sum += __shfl_xor_sync(0xffffffffu, sum, 4);
            float mean = sum * 0.015625f;
            float sq = 0.f;
            #pragma unroll
            for (int i = 0; i < 8; i++) { float dd = r[i] - mean; sq = fmaf(dd, dd, sq); }
            sq += __shfl_xor_sync(0xffffffffu, sq, 1);
            sq += __shfl_xor_sync(0xffffffffu, sq, 2);
            sq += __shfl_xor_sync(0xffffffffu, sq, 4);
            float inv = rsqrtf(sq * 0.015625f + 1e-5f);
            #pragma unroll
            for (int i = 0; i < 8; i++) {
                int j = g + 8 * i;
                srw[j] = (r[i] - mean) * inv * ln1w[j] + ln1b[j];
            }
        }
        __syncwarp();

        // ---- FF1 + exact gelu ----
        {
            float ga[16];
            #pragma unroll
            for (int i = 0; i < 16; i++) ga[i] = b1[g + 8 * i];
            for (int k = 0; k < 64; k++) {
                float xk = srow[k];
                const float* wr = W1 + k * 128 + g;
                #pragma unroll
                for (int i = 0; i < 16; i++) ga[i] = fmaf(xk, wr[8 * i], ga[i]);
            }
            #pragma unroll
            for (int i = 0; i < 16; i++) {
                float xg = ga[i];
                b2f[t * 128 + g + 8 * i] = 0.5f * xg * (1.0f + erff(xg * 0.70710678118f));
            }
        }
        __syncwarp();

        // ---- FF2 + residual + LN2 + token mean ----
        {
            float f[8];
            #pragma unroll
            for (int i = 0; i < 8; i++) f[i] = b2[g + 8 * i];
            const float* grow = b2f + t * 128;
            for (int k = 0; k < 128; k++) {
                float gk = grow[k];
                const float* wr = W2 + k * 64 + g;
                #pragma unroll
                for (int i = 0; i < 8; i++) f[i] = fmaf(gk, wr[8 * i], f[i]);
            }
            float sum = 0.f;
            #pragma unroll
            for (int i = 0; i < 8; i++) { f[i] += srow[g + 8 * i]; sum += f[i]; }
            sum += __shfl_xor_sync(0xffffffffu, sum, 1);
            sum += __shfl_xor_sync(0xffffffffu, sum, 2);
            sum += __shfl_xor_sync(0xffffffffu, sum, 4);
            float mean = sum * 0.015625f;
            float sq = 0.f;
            #pragma unroll
            for (int i = 0; i < 8; i++) { float dd = f[i] - mean; sq = fmaf(dd, dd, sq); }
            sq += __shfl_xor_sync(0xffffffffu, sq, 1);
            sq += __shfl_xor_sync(0xffffffffu, sq, 2);
            sq += __shfl_xor_sync(0xffffffffu, sq, 4);
            float inv = rsqrtf(sq * 0.015625f + 1e-5f);
            #pragma unroll
            for (int i = 0; i < 8; i++) {
                int j = g + 8 * i;
                float x2 = (f[i] - mean) * inv * ln2w[j] + ln2b[j];
                x2 += __shfl_xor_sync(0xffffffffu, x2, 8);
                x2 += __shfl_xor_sync(0xffffffffu, x2, 16);
                if (t == 0) hb[j] = x2 * 0.25f;
            }
        }
        __syncwarp();

        // ---- classifier: 40 outputs ----
        {
            float o0 = bcls[l];
            float o1 = (l < 8) ? bcls[32 + l] : 0.f;
            for (int k = 0; k < 64; k++) {
                float hk = hb[k];
                o0 = fmaf(hk, Wcls[k * 40 + l], o0);
                o1 = fmaf(hk, Wcls[k * 40 + 32 + (l & 7)], o1);
            }
            out[(size_t)n * 40 + l] = o0;
            if (l < 8) out[(size_t)n * 40 + 32 + l] = o1;
        }
        __syncwarp();
    }
}

extern "C" void kernel_launch(void* const* d_in, const int* in_sizes, int n_in,
                              void* d_out, int out_size) {
    const float* x     = (const float*)d_in[0];
    const int*   ei    = (const int*)d_in[1];
    const float* W_in  = (const float*)d_in[2];
    const float* b_in  = (const float*)d_in[3];
    const float* sg_W  = (const float*)d_in[4];
    const float* sg_b  = (const float*)d_in[5];
    const float* Wqkv  = (const float*)d_in[6];
    const float* bqkv  = (const float*)d_in[7];
    const float* Wout  = (const float*)d_in[8];
    const float* bout  = (const float*)d_in[9];
    const float* W1    = (const float*)d_in[10];
    const float* b1    = (const float*)d_in[11];
    const float* W2    = (const float*)d_in[12];
    const float* b2    = (const float*)d_in[13];
    const float* ln1w  = (const float*)d_in[14];
    const float* ln1b  = (const float*)d_in[15];
    const float* ln2w  = (const float*)d_in[16];
    const float* ln2b  = (const float*)d_in[17];
    const float* Wcls  = (const float*)d_in[18];
    const float* bcls  = (const float*)d_in[19];
    float* out = (float*)d_out;

    cudaFuncSetAttribute(k_in_linear, cudaFuncAttributeMaxDynamicSharedMemorySize, 99584);
    cudaFuncSetAttribute(k_former,    cudaFuncAttributeMaxDynamicSharedMemorySize, 196000);

    // degree / dinv
    k_deg_init<<<(Nn + 255) / 256, 256>>>();
    k_deg_acc<<<(Ee + 255) / 256, 256>>>(ei + Ee);
    k_deg_fin<<<(Nn + 255) / 256, 256>>>();

    // h0 + seq slot 0
    k_in_linear<<<592, 256, 99584>>>(x, W_in, b_in);

    // 3 hops: buffers 0 -> 1 -> 2 -> 1
    const int inb[3]  = {0, 1, 2};
    const int outb[3] = {1, 2, 1};
    for (int hop = 0; hop < 3; hop++) {
        k_prop_init<<<(NH / 4 + 255) / 256, 256>>>(inb[hop], outb[hop]);
        k_prop_edges<<<(Ee * 16) / 256, 256>>>(ei, ei + Ee, inb[hop], outb[hop]);
        k_tok<<<1024, 256>>>(outb[hop], sg_W + hop * 4096, sg_b + hop * 64, hop + 1);
    }

    // fused transformer + pooling + classifier — single balanced wave (148 SMs, 1 CTA/SM)
    k_former<<<148, 256, 196000>>>(Wqkv, bqkv, Wout, bout, W1, b1, W2, b2,
                                   ln1w, ln1b, ln2w, ln2b, Wcls, bcls, out);
}

// round 5
// speedup vs baseline: 1.9619x; 1.2956x over previous
#include <cuda_runtime.h>
#include <math.h>

#define Nn   100000
#define Ee   1600000
#define NH   (Nn * 64)

// Scratch (static device globals; no allocations allowed)
__device__ float g_dinv[Nn];
__device__ float g_hb[3][NH];
__device__ float g_seq[(size_t)Nn * 256];
__device__ float g_Mt[4096];   // Mt[b*64+a] = (Wq^T Wk)[a,b]
__device__ float g_Wvo[4096];  // Wvo[b*64+a] = (Wout Wv)[a,b]
__device__ float g_p2[64];     // p2[b] = sum_j bq[j]*Wk[j][b]
__device__ float g_bvo[64];    // bvo[a] = Wout bv + bout

// ---------------- degree / norm ----------------
__global__ void k_deg_init() {
    int i = blockIdx.x * blockDim.x + threadIdx.x;
    if (i < Nn) g_dinv[i] = 1.0f;
}
__global__ void k_deg_acc(const int* __restrict__ dst) {
    int e = blockIdx.x * blockDim.x + threadIdx.x;
    if (e < Ee) atomicAdd(&g_dinv[dst[e]], 1.0f);
}
__global__ void k_deg_fin() {
    int i = blockIdx.x * blockDim.x + threadIdx.x;
    if (i < Nn) g_dinv[i] = rsqrtf(g_dinv[i]);
}

// ---------------- h0 = relu(x @ W_in^T + b_in) ----------------
__global__ void k_in_linear(const float* __restrict__ x, const float* __restrict__ W,
                            const float* __restrict__ b) {
    extern __shared__ float sm[];
    float* Ws = sm;                 // [64][260]
    float* bb = Ws + 64 * 260;
    float* xb = bb + 64;
    int tid = threadIdx.x;
    for (int i = tid; i < 64 * 64; i += 256) {
        int j = i >> 6, q = i & 63;
        ((float4*)(Ws + j * 260))[q] = ((const float4*)(W + j * 256))[q];
    }
    if (tid < 64) bb[tid] = b[tid];
    __syncthreads();
    int warp = tid >> 5, l = tid & 31;
    float* xw = xb + warp * 1024;
    const float* w0p = Ws + l * 260;
    const float* w1p = Ws + (l + 32) * 260;
    for (int grp = blockIdx.x * 8 + warp; grp < 25000; grp += gridDim.x * 8) {
        int row0 = grp * 4;
        const float4* xg = (const float4*)(x + (size_t)row0 * 256);
        #pragma unroll
        for (int r = 0; r < 4; r++) {
            ((float4*)xw)[r * 64 + l]      = xg[r * 64 + l];
            ((float4*)xw)[r * 64 + l + 32] = xg[r * 64 + l + 32];
        }
        __syncwarp();
        float acc0[4], acc1[4];
        #pragma unroll
        for (int r = 0; r < 4; r++) { acc0[r] = bb[l]; acc1[r] = bb[l + 32]; }
        #pragma unroll 4
        for (int k4 = 0; k4 < 64; k4++) {
            float4 wa = ((const float4*)w0p)[k4];
            float4 wb = ((const float4*)w1p)[k4];
            #pragma unroll
            for (int r = 0; r < 4; r++) {
                float4 xv = ((const float4*)(xw + r * 256))[k4];
                acc0[r] = fmaf(xv.x, wa.x, acc0[r]);
                acc0[r] = fmaf(xv.y, wa.y, acc0[r]);
                acc0[r] = fmaf(xv.z, wa.z, acc0[r]);
                acc0[r] = fmaf(xv.w, wa.w, acc0[r]);
                acc1[r] = fmaf(xv.x, wb.x, acc1[r]);
                acc1[r] = fmaf(xv.y, wb.y, acc1[r]);
                acc1[r] = fmaf(xv.z, wb.z, acc1[r]);
                acc1[r] = fmaf(xv.w, wb.w, acc1[r]);
            }
        }
        #pragma unroll
        for (int r = 0; r < 4; r++) {
            float a0 = fmaxf(acc0[r], 0.f), a1 = fmaxf(acc1[r], 0.f);
            size_t row = row0 + r;
            g_hb[0][row * 64 + l]      = a0;
            g_hb[0][row * 64 + l + 32] = a1;
            g_seq[row * 256 + l]       = a0;
            g_seq[row * 256 + l + 32]  = a1;
        }
        __syncwarp();
    }
}

// ---------------- propagation (scatter + RED, proven) ----------------
__global__ void k_prop_init(int inb, int outb) {
    int idx = blockIdx.x * blockDim.x + threadIdx.x;
    if (idx < NH / 4) {
        float d = g_dinv[idx >> 4];
        float w = d * d;
        float4 v = ((const float4*)g_hb[inb])[idx];
        v.x *= w; v.y *= w; v.z *= w; v.w *= w;
        ((float4*)g_hb[outb])[idx] = v;
    }
}

__global__ void k_prop_edges(const int* __restrict__ src, const int* __restrict__ dst,
                             int inb, int outb) {
    long tid = (long)blockIdx.x * blockDim.x + threadIdx.x;
    int e = (int)(tid >> 4);
    if (e >= Ee) return;
    int q = (int)tid & 15;
    int s = __ldg(src + e), d = __ldg(dst + e);
    float w = g_dinv[s] * g_dinv[d];
    float4 v = ((const float4*)(g_hb[inb] + (size_t)s * 64))[q];
    float* p = g_hb[outb] + (size_t)d * 64 + q * 4;
    asm volatile("red.global.add.v4.f32 [%0], {%1,%2,%3,%4};"
                 :: "l"(p), "f"(v.x * w), "f"(v.y * w), "f"(v.z * w), "f"(v.w * w)
                 : "memory");
}

// ---------------- token = relu(p @ sg_W[k]^T + sg_b[k]) ----------------
__global__ void k_tok(int inb, const float* __restrict__ W, const float* __restrict__ b, int slot) {
    __shared__ float Wt[4096];
    __shared__ float bb[64];
    __shared__ float xb[8 * 64];
    int tid = threadIdx.x;
    for (int i = tid; i < 4096; i += 256) {
        int k = i >> 6, j = i & 63;
        Wt[i] = W[j * 64 + k];
    }
    if (tid < 64) bb[tid] = b[tid];
    __syncthreads();
    int warp = tid >> 5, l = tid & 31;
    float* xw = xb + warp * 64;
    const float* pin = g_hb[inb];
    for (int row = blockIdx.x * 8 + warp; row < Nn; row += gridDim.x * 8) {
        xw[l]      = pin[(size_t)row * 64 + l];
        xw[l + 32] = pin[(size_t)row * 64 + l + 32];
        __syncwarp();
        float a0 = bb[l], a1 = bb[l + 32];
        #pragma unroll 8
        for (int k = 0; k < 64; k++) {
            float xk = xw[k];
            a0 = fmaf(xk, Wt[k * 64 + l],      a0);
            a1 = fmaf(xk, Wt[k * 64 + l + 32], a1);
        }
        float* op = g_seq + (size_t)row * 256 + slot * 64;
        op[l]      = fmaxf(a0, 0.f);
        op[l + 32] = fmaxf(a1, 0.f);
        __syncwarp();
    }
}

// ---------------- precompute folded attention matrices ----------------
__global__ void k_pre(const float* __restrict__ inW, const float* __restrict__ inb,
                      const float* __restrict__ WoutG, const float* __restrict__ boutG) {
    int e = blockIdx.x * blockDim.x + threadIdx.x;
    if (e < 4096) {
        int bcol = e >> 6, a = e & 63;
        float m = 0.f, wv = 0.f;
        for (int j = 0; j < 64; j++) {
            m  = fmaf(__ldg(inW + j * 64 + a),   __ldg(inW + (64 + j) * 64 + bcol), m);
            wv = fmaf(__ldg(WoutG + a * 64 + j), __ldg(inW + (128 + j) * 64 + bcol), wv);
        }
        g_Mt[e] = m;
        g_Wvo[e] = wv;
    }
    if (e < 64) {
        float p = 0.f;
        for (int j = 0; j < 64; j++) p = fmaf(__ldg(inb + j), __ldg(inW + (64 + j) * 64 + e), p);
        g_p2[e] = p;
    } else if (e < 128) {
        int a = e - 64;
        float bv = __ldg(boutG + a);
        for (int j = 0; j < 64; j++) bv = fmaf(__ldg(WoutG + a * 64 + j), __ldg(inb + 128 + j), bv);
        g_bvo[a] = bv;
    }
}

// ================= fused transformer + mean + classifier =================
// 12 warps/CTA, 1 warp/node. Lane: t = l>>3 (token), g = l&7.
// CONFLICT-FREE mapping: lane g owns output word-chunks 4g and 32+4g.
#define SSTR 68     // token stride for s, z buffers
#define FSTR 136    // token stride for b2f buffer
#define WSCR 1168   // per-warp scratch floats

__global__ void __launch_bounds__(384, 1) k_former(
    const float* __restrict__ W1_g,   const float* __restrict__ b1_g,
    const float* __restrict__ W2_g,   const float* __restrict__ b2_g,
    const float* __restrict__ ln1w_g, const float* __restrict__ ln1b_g,
    const float* __restrict__ ln2w_g, const float* __restrict__ ln2b_g,
    const float* __restrict__ Wcls_g, const float* __restrict__ bcls_g,
    float* __restrict__ out)
{
    extern __shared__ float sm[];
    float* MtS   = sm;              // [64][64]  MtS[k*64+j]
    float* WvoS  = MtS + 4096;      // [64][64]
    float* W1S   = WvoS + 4096;     // [64][128]
    float* W2S   = W1S + 8192;      // [128][64]
    float* WclsS = W2S + 8192;      // [64][40]
    float* p2S   = WclsS + 2560;    // 64
    float* bvoS  = p2S + 64;        // 64
    float* b1S   = bvoS + 64;       // 128
    float* b2S   = b1S + 128;       // 64
    float* bclsS = b2S + 64;        // 40
    float* ln1wS = bclsS + 40;      // 64
    float* ln1bS = ln1wS + 64;
    float* ln2wS = ln1bS + 64;
    float* ln2bS = ln2wS + 64;
    float* scratch = ln2bS + 64;    // 12 * WSCR

    int tid = threadIdx.x;
    for (int i = tid; i < 4096; i += 384) { MtS[i] = g_Mt[i]; WvoS[i] = g_Wvo[i]; }
    for (int i = tid; i < 8192; i += 384) { int j = i & 127, k = i >> 7; W1S[k * 128 + j] = W1_g[j * 64 + k]; }
    for (int i = tid; i < 8192; i += 384) { int j = i & 63,  k = i >> 6; W2S[k * 64 + j]  = W2_g[j * 128 + k]; }
    for (int i = tid; i < 2560; i += 384) { int j = i % 40,  k = i / 40; WclsS[k * 40 + j] = Wcls_g[j * 64 + k]; }
    if (tid < 64) {
        p2S[tid] = g_p2[tid]; bvoS[tid] = g_bvo[tid]; b2S[tid] = b2_g[tid];
        ln1wS[tid] = ln1w_g[tid]; ln1bS[tid] = ln1b_g[tid];
        ln2wS[tid] = ln2w_g[tid]; ln2bS[tid] = ln2b_g[tid];
    }
    if (tid >= 64 && tid < 192) b1S[tid - 64] = b1_g[tid - 64];
    if (tid >= 192 && tid < 232) bclsS[tid - 192] = bcls_g[tid - 192];
    __syncthreads();

    int warp = tid >> 5, l = tid & 31;
    float* s   = scratch + warp * WSCR;  // 4*68
    float* z   = s + 272;                // 4*68
    float* b2f = z + 272;                // 4*136
    float* sc  = b2f + 544;              // 16
    float* hb  = sc + 16;                // 64
    const int t = l >> 3, g = l & 7;
    float* srow = s + t * SSTR;
    const int c1 = 4 * g, c2 = 32 + 4 * g;

    for (int n = blockIdx.x * 12 + warp; n < Nn; n += gridDim.x * 12) {
        // load seq [4][64] into padded s
        {
            const float4* sp = (const float4*)(g_seq + (size_t)n * 256);
            int t0 = l >> 4, m = l & 15;            // first 2 tokens
            float4 v0 = sp[l], v1 = sp[l + 32];
            ((float4*)(s + t0 * SSTR))[m] = v0;
            ((float4*)(s + (t0 + 2) * SSTR))[m] = v1;
        }
        __syncwarp();

        // ---- z_t = M s_t ----
        {
            float4 a0 = make_float4(0.f,0.f,0.f,0.f), a1 = a0;
            #pragma unroll 4
            for (int k4 = 0; k4 < 16; k4++) {
                float4 xv = ((const float4*)srow)[k4];
                #pragma unroll
                for (int kk = 0; kk < 4; kk++) {
                    const float* wrow = MtS + (k4 * 4 + kk) * 64;
                    float4 wA = *(const float4*)(wrow + c1);
                    float4 wB = *(const float4*)(wrow + c2);
                    float xk = kk == 0 ? xv.x : kk == 1 ? xv.y : kk == 2 ? xv.z : xv.w;
                    a0.x = fmaf(xk, wA.x, a0.x); a0.y = fmaf(xk, wA.y, a0.y);
                    a0.z = fmaf(xk, wA.z, a0.z); a0.w = fmaf(xk, wA.w, a0.w);
                    a1.x = fmaf(xk, wB.x, a1.x); a1.y = fmaf(xk, wB.y, a1.y);
                    a1.z = fmaf(xk, wB.z, a1.z); a1.w = fmaf(xk, wB.w, a1.w);
                }
            }
            *(float4*)(z + t * SSTR + c1) = a0;
            *(float4*)(z + t * SSTR + c2) = a1;
        }
        __syncwarp();

        // ---- scores + softmax (bias terms constant in softmax axis dropped) ----
        if (l < 16) {
            int ss = l >> 2, tt = l & 3;
            const float4* ap = (const float4*)(s + ss * SSTR);
            const float4* zp = (const float4*)(z + tt * SSTR);
            const float4* bp = (const float4*)(s + tt * SSTR);
            const float4* pp = (const float4*)p2S;
            float d = 0.f;
            #pragma unroll 4
            for (int k4 = 0; k4 < 16; k4++) {
                float4 a = ap[k4], zz = zp[k4], bq = bp[k4], p = pp[k4];
                d += a.x * zz.x + a.y * zz.y + a.z * zz.z + a.w * zz.w;
                d += p.x * bq.x + p.y * bq.y + p.z * bq.z + p.w * bq.w;
            }
            sc[l] = d * 0.125f;
        }
        __syncwarp();
        if (l < 4) {
            float s0 = sc[l*4], s1 = sc[l*4+1], s2 = sc[l*4+2], s3 = sc[l*4+3];
            float m = fmaxf(fmaxf(s0, s1), fmaxf(s2, s3));
            float e0 = __expf(s0 - m), e1 = __expf(s1 - m), e2 = __expf(s2 - m), e3 = __expf(s3 - m);
            float inv = 1.f / (e0 + e1 + e2 + e3);
            sc[l*4] = e0*inv; sc[l*4+1] = e1*inv; sc[l*4+2] = e2*inv; sc[l*4+3] = e3*inv;
        }
        __syncwarp();

        // ---- m_t = sum_c P[t,c] s_c  (into b2f) ----
        {
            float w0 = sc[t*4], w1 = sc[t*4+1], w2 = sc[t*4+2], w3 = sc[t*4+3];
            #pragma unroll
            for (int h = 0; h < 2; h++) {
                int c = h == 0 ? c1 : c2;
                float4 s0 = *(const float4*)(s + c);
                float4 s1 = *(const float4*)(s + SSTR + c);
                float4 s2 = *(const float4*)(s + 2 * SSTR + c);
                float4 s3 = *(const float4*)(s + 3 * SSTR + c);
                float4 r;
                r.x = w0*s0.x + w1*s1.x + w2*s2.x + w3*s3.x;
                r.y = w0*s0.y + w1*s1.y + w2*s2.y + w3*s3.y;
                r.z = w0*s0.z + w1*s1.z + w2*s2.z + w3*s3.z;
                r.w = w0*s0.w + w1*s1.w + w2*s2.w + w3*s3.w;
                *(float4*)(b2f + t * FSTR + c) = r;
            }
        }
        __syncwarp();

        // ---- out = Wvo m + bvo, residual, LN1 (back into srow) ----
        {
            float4 r0 = *(const float4*)(bvoS + c1);
            float4 r1 = *(const float4*)(bvoS + c2);
            const float* arow = b2f + t * FSTR;
            #pragma unroll 4
            for (int k4 = 0; k4 < 16; k4++) {
                float4 av = ((const float4*)arow)[k4];
                #pragma unroll
                for (int kk = 0; kk < 4; kk++) {
                    const float* wrow = WvoS + (k4 * 4 + kk) * 64;
                    float4 wA = *(const float4*)(wrow + c1);
                    float4 wB = *(const float4*)(wrow + c2);
                    float ak = kk == 0 ? av.x : kk == 1 ? av.y : kk == 2 ? av.z : av.w;
                    r0.x = fmaf(ak, wA.x, r0.x); r0.y = fmaf(ak, wA.y, r0.y);
                    r0.z = fmaf(ak, wA.z, r0.z); r0.w = fmaf(ak, wA.w, r0.w);
                    r1.x = fmaf(ak, wB.x, r1.x); r1.y = fmaf(ak, wB.y, r1.y);
                    r1.z = fmaf(ak, wB.z, r1.z); r1.w = fmaf(ak, wB.w, r1.w);
                }
            }
            float4 rs0 = *(const float4*)(srow + c1);
            float4 rs1 = *(const float4*)(srow + c2);
            r0.x += rs0.x; r0.y += rs0.y; r0.z += rs0.z; r0.w += rs0.w;
            r1.x += rs1.x; r1.y += rs1.y; r1.z += rs1.z; r1.w += rs1.w;
            float sum = r0.x + r0.y + r0.z + r0.w + r1.x + r1.y + r1.z + r1.w;
            sum += __shfl_xor_sync(0xffffffffu, sum, 1);
            sum += __shfl_xor_sync(0xffffffffu, sum, 2);
            sum += __shfl_xor_sync(0xffffffffu, sum, 4);
            float mean = sum * 0.015625f;
            float d0 = r0.x-mean, d1 = r0.y-mean, d2 = r0.z-mean, d3 = r0.w-mean;
            float d4 = r1.x-mean, d5 = r1.y-mean, d6 = r1.z-mean, d7 = r1.w-mean;
            float sq = d0*d0 + d1*d1 + d2*d2 + d3*d3 + d4*d4 + d5*d5 + d6*d6 + d7*d7;
            sq += __shfl_xor_sync(0xffffffffu, sq, 1);
            sq += __shfl_xor_sync(0xffffffffu, sq, 2);
            sq += __shfl_xor_sync(0xffffffffu, sq, 4);
            float inv = rsqrtf(sq * 0.015625f + 1e-5f);
            float4 wA = *(const float4*)(ln1wS + c1), wB = *(const float4*)(ln1wS + c2);
            float4 bA = *(const float4*)(ln1bS + c1), bB = *(const float4*)(ln1bS + c2);
            float4 o0, o1;
            o0.x = d0*inv*wA.x + bA.x; o0.y = d1*inv*wA.y + bA.y;
            o0.z = d2*inv*wA.z + bA.z; o0.w = d3*inv*wA.w + bA.w;
            o1.x = d4*inv*wB.x + bB.x; o1.y = d5*inv*wB.y + bB.y;
            o1.z = d6*inv*wB.z + bB.z; o1.w = d7*inv*wB.w + bB.w;
            *(float4*)(srow + c1) = o0;
            *(float4*)(srow + c2) = o1;
        }
        __syncwarp();

        // ---- FF1 + exact gelu (into b2f, 128 wide) ----
        {
            float4 ga[4];
            #pragma unroll
            for (int i = 0; i < 4; i++) ga[i] = *(const float4*)(b1S + 32 * i + c1);
            #pragma unroll 2
            for (int k4 = 0; k4 < 16; k4++) {
                float4 xv = ((const float4*)srow)[k4];
                #pragma unroll
                for (int kk = 0; kk < 4; kk++) {
                    const float* wrow = W1S + (k4 * 4 + kk) * 128;
                    float xk = kk == 0 ? xv.x : kk == 1 ? xv.y : kk == 2 ? xv.z : xv.w;
                    #pragma unroll
                    for (int i = 0; i < 4; i++) {
                        float4 w = *(const float4*)(wrow + 32 * i + c1);
                        ga[i].x = fmaf(xk, w.x, ga[i].x); ga[i].y = fmaf(xk, w.y, ga[i].y);
                        ga[i].z = fmaf(xk, w.z, ga[i].z); ga[i].w = fmaf(xk, w.w, ga[i].w);
                    }
                }
            }
            float* gp = b2f + t * FSTR;
            #pragma unroll
            for (int i = 0; i < 4; i++) {
                float4 v = ga[i];
                v.x = 0.5f * v.x * (1.0f + erff(v.x * 0.70710678118f));
                v.y = 0.5f * v.y * (1.0f + erff(v.y * 0.70710678118f));
                v.z = 0.5f * v.z * (1.0f + erff(v.z * 0.70710678118f));
                v.w = 0.5f * v.w * (1.0f + erff(v.w * 0.70710678118f));
                *(float4*)(gp + 32 * i + c1) = v;
            }
        }
        __syncwarp();

        // ---- FF2 + residual + LN2 + token mean ----
        {
            float4 f0 = *(const float4*)(b2S + c1);
            float4 f1 = *(const float4*)(b2S + c2);
            const float* grow = b2f + t * FSTR;
            #pragma unroll 2
            for (int k4 = 0; k4 < 32; k4++) {
                float4 gv = ((const float4*)grow)[k4];
                #pragma unroll
                for (int kk = 0; kk < 4; kk++) {
                    const float* wrow = W2S + (k4 * 4 + kk) * 64;
                    float4 wA = *(const float4*)(wrow + c1);
                    float4 wB = *(const float4*)(wrow + c2);
                    float gk = kk == 0 ? gv.x : kk == 1 ? gv.y : kk == 2 ? gv.z : gv.w;
                    f0.x = fmaf(gk, wA.x, f0.x); f0.y = fmaf(gk, wA.y, f0.y);
                    f0.z = fmaf(gk, wA.z, f0.z); f0.w = fmaf(gk, wA.w, f0.w);
                    f1.x = fmaf(gk, wB.x, f1.x); f1.y = fmaf(gk, wB.y, f1.y);
                    f1.z = fmaf(gk, wB.z, f1.z); f1.w = fmaf(gk, wB.w, f1.w);
                }
            }
            float4 rs0 = *(const float4*)(srow + c1);
            float4 rs1 = *(const float4*)(srow + c2);
            f0.x += rs0.x; f0.y += rs0.y; f0.z += rs0.z; f0.w += rs0.w;
            f1.x += rs1.x; f1.y += rs1.y; f1.z += rs1.z; f1.w += rs1.w;
            float sum = f0.x + f0.y + f0.z + f0.w + f1.x + f1.y + f1.z + f1.w;
            sum += __shfl_xor_sync(0xffffffffu, sum, 1);
            sum += __shfl_xor_sync(0xffffffffu, sum, 2);
            sum += __shfl_xor_sync(0xffffffffu, sum, 4);
            float mean = sum * 0.015625f;
            float d0 = f0.x-mean, d1 = f0.y-mean, d2 = f0.z-mean, d3 = f0.w-mean;
            float d4 = f1.x-mean, d5 = f1.y-mean, d6 = f1.z-mean, d7 = f1.w-mean;
            float sq = d0*d0 + d1*d1 + d2*d2 + d3*d3 + d4*d4 + d5*d5 + d6*d6 + d7*d7;
            sq += __shfl_xor_sync(0xffffffffu, sq, 1);
            sq += __shfl_xor_sync(0xffffffffu, sq, 2);
            sq += __shfl_xor_sync(0xffffffffu, sq, 4);
            float inv = rsqrtf(sq * 0.015625f + 1e-5f);
            float4 wA = *(const float4*)(ln2wS + c1), wB = *(const float4*)(ln2wS + c2);
            float4 bA = *(const float4*)(ln2bS + c1), bB = *(const float4*)(ln2bS + c2);
            float x2[8];
            x2[0] = d0*inv*wA.x + bA.x; x2[1] = d1*inv*wA.y + bA.y;
            x2[2] = d2*inv*wA.z + bA.z; x2[3] = d3*inv*wA.w + bA.w;
            x2[4] = d4*inv*wB.x + bB.x; x2[5] = d5*inv*wB.y + bB.y;
            x2[6] = d6*inv*wB.z + bB.z; x2[7] = d7*inv*wB.w + bB.w;
            #pragma unroll
            for (int i = 0; i < 8; i++) {
                float v = x2[i];
                v += __shfl_xor_sync(0xffffffffu, v, 8);
                v += __shfl_xor_sync(0xffffffffu, v, 16);
                x2[i] = v * 0.25f;
            }
            if (t == 0) {
                *(float4*)(hb + c1) = make_float4(x2[0], x2[1], x2[2], x2[3]);
                *(float4*)(hb + c2) = make_float4(x2[4], x2[5], x2[6], x2[7]);
            }
        }
        __syncwarp();

        // ---- classifier: 40 outputs ----
        {
            float o0 = bclsS[l];
            float o1 = bclsS[32 + g];
            #pragma unroll 4
            for (int k4 = 0; k4 < 16; k4++) {
                float4 hv = ((const float4*)hb)[k4];
                const float* wr = WclsS + k4 * 160;
                o0 = fmaf(hv.x, wr[l], o0);        o1 = fmaf(hv.x, wr[32 + g], o1);
                o0 = fmaf(hv.y, wr[40 + l], o0);   o1 = fmaf(hv.y, wr[72 + g], o1);
                o0 = fmaf(hv.z, wr[80 + l], o0);   o1 = fmaf(hv.z, wr[112 + g], o1);
                o0 = fmaf(hv.w, wr[120 + l], o0);  o1 = fmaf(hv.w, wr[152 + g], o1);
            }
            out[(size_t)n * 40 + l] = o0;
            if (l < 8) out[(size_t)n * 40 + 32 + l] = o1;
        }
        __syncwarp();
    }
}

extern "C" void kernel_launch(void* const* d_in, const int* in_sizes, int n_in,
                              void* d_out, int out_size) {
    const float* x     = (const float*)d_in[0];
    const int*   ei    = (const int*)d_in[1];
    const float* W_in  = (const float*)d_in[2];
    const float* b_in  = (const float*)d_in[3];
    const float* sg_W  = (const float*)d_in[4];
    const float* sg_b  = (const float*)d_in[5];
    const float* inW   = (const float*)d_in[6];
    const float* inb   = (const float*)d_in[7];
    const float* Wout  = (const float*)d_in[8];
    const float* bout  = (const float*)d_in[9];
    const float* W1    = (const float*)d_in[10];
    const float* b1    = (const float*)d_in[11];
    const float* W2    = (const float*)d_in[12];
    const float* b2    = (const float*)d_in[13];
    const float* ln1w  = (const float*)d_in[14];
    const float* ln1b  = (const float*)d_in[15];
    const float* ln2w  = (const float*)d_in[16];
    const float* ln2b  = (const float*)d_in[17];
    const float* Wcls  = (const float*)d_in[18];
    const float* bcls  = (const float*)d_in[19];
    float* out = (float*)d_out;

    // smem: weights 27752 + 12*1168 = 41768 floats = 167072 B
    cudaFuncSetAttribute(k_in_linear, cudaFuncAttributeMaxDynamicSharedMemorySize, 99584);
    cudaFuncSetAttribute(k_former,    cudaFuncAttributeMaxDynamicSharedMemorySize, 167072);

    // degree / dinv
    k_deg_init<<<(Nn + 255) / 256, 256>>>();
    k_deg_acc<<<(Ee + 255) / 256, 256>>>(ei + Ee);
    k_deg_fin<<<(Nn + 255) / 256, 256>>>();

    // h0 + seq slot 0
    k_in_linear<<<592, 256, 99584>>>(x, W_in, b_in);

    // folded attention matrices
    k_pre<<<16, 256>>>(inW, inb, Wout, bout);

    // 3 hops
    const int inb_[3]  = {0, 1, 2};
    const int outb_[3] = {1, 2, 1};
    for (int hop = 0; hop < 3; hop++) {
        k_prop_init<<<(NH / 4 + 255) / 256, 256>>>(inb_[hop], outb_[hop]);
        k_prop_edges<<<(Ee * 16) / 256, 256>>>(ei, ei + Ee, inb_[hop], outb_[hop]);
        k_tok<<<1024, 256>>>(outb_[hop], sg_W + hop * 4096, sg_b + hop * 64, hop + 1);
    }

    // fused transformer + pooling + classifier — single wave, 12 warps/CTA
    k_former<<<148, 384, 167072>>>(W1, b1, W2, b2, ln1w, ln1b, ln2w, ln2b, Wcls, bcls, out);
}

// round 6
// speedup vs baseline: 2.1620x; 1.1020x over previous
#include <cuda_runtime.h>
#include <math.h>

#define Nn   100000
#define Ee   1600000
#define NH   (Nn * 64)
#define NB_SCAN 98   // ceil(100000/1024)

// ---- persistent device scratch ----
__device__ float g_dinv[Nn];
__device__ int   g_cnt[Nn];
__device__ int   g_off[Nn];
__device__ int   g_cur[Nn];
__device__ int   g_bsum[128];
__device__ int2  g_csr[Ee];
__device__ float g_hb[3][NH];
__device__ float g_seq[(size_t)Nn * 256];
__device__ float g_Mt[4096];   // (Wq^T Wk)[a,b] at [b*64+a]
__device__ float g_Wvo[4096];  // (Wout Wv)[a,b] at [b*64+a]
__device__ float g_p2[64];
__device__ float g_bvo[64];

// ================= CSR build + dinv =================
__global__ void k_init() {
    int i = blockIdx.x * blockDim.x + threadIdx.x;
    if (i < Nn) g_cnt[i] = 0;
}
__global__ void k_count(const int* __restrict__ dst) {
    int e = blockIdx.x * blockDim.x + threadIdx.x;
    if (e < Ee) atomicAdd(&g_cnt[dst[e]], 1);
}
__global__ void k_scan1() {
    __shared__ int smv[1024];
    int i = blockIdx.x * 1024 + threadIdx.x;
    int v = (i < Nn) ? g_cnt[i] : 0;
    smv[threadIdx.x] = v;
    __syncthreads();
    for (int off = 1; off < 1024; off <<= 1) {
        int t = 0;
        if (threadIdx.x >= off) t = smv[threadIdx.x - off];
        __syncthreads();
        if (threadIdx.x >= off) smv[threadIdx.x] += t;
        __syncthreads();
    }
    if (i < Nn) g_off[i] = smv[threadIdx.x];
    if (threadIdx.x == 1023) g_bsum[blockIdx.x] = smv[1023];
}
__global__ void k_scan2() {
    int acc = 0;
    for (int b = 0; b < NB_SCAN; b++) { int t = g_bsum[b]; g_bsum[b] = acc; acc += t; }
}
__global__ void k_scan3() {
    int i = blockIdx.x * 1024 + threadIdx.x;
    if (i < Nn) {
        int incl = g_off[i] + g_bsum[i >> 10];
        int excl = incl - g_cnt[i];
        g_off[i] = excl;
        g_cur[i] = excl;
        g_dinv[i] = rsqrtf((float)g_cnt[i] + 1.0f);
    }
}
__global__ void k_fill(const int* __restrict__ src, const int* __restrict__ dst) {
    int e = blockIdx.x * blockDim.x + threadIdx.x;
    if (e < Ee) {
        int s = src[e], d = dst[e];
        int pos = atomicAdd(&g_cur[d], 1);
        g_csr[pos] = make_int2(s, __float_as_int(g_dinv[s]));
    }
}

// ================= h0 = relu(x @ W_in^T + b_in) =================
__global__ void k_in_linear(const float* __restrict__ x, const float* __restrict__ W,
                            const float* __restrict__ b) {
    extern __shared__ float sm[];
    float* Ws = sm;                 // [64][260]
    float* bb = Ws + 64 * 260;
    float* xb = bb + 64;
    int tid = threadIdx.x;
    for (int i = tid; i < 64 * 64; i += 256) {
        int j = i >> 6, q = i & 63;
        ((float4*)(Ws + j * 260))[q] = ((const float4*)(W + j * 256))[q];
    }
    if (tid < 64) bb[tid] = b[tid];
    __syncthreads();
    int warp = tid >> 5, l = tid & 31;
    float* xw = xb + warp * 1024;
    const float* w0p = Ws + l * 260;
    const float* w1p = Ws + (l + 32) * 260;
    for (int grp = blockIdx.x * 8 + warp; grp < 25000; grp += gridDim.x * 8) {
        int row0 = grp * 4;
        const float4* xg = (const float4*)(x + (size_t)row0 * 256);
        #pragma unroll
        for (int r = 0; r < 4; r++) {
            ((float4*)xw)[r * 64 + l]      = xg[r * 64 + l];
            ((float4*)xw)[r * 64 + l + 32] = xg[r * 64 + l + 32];
        }
        __syncwarp();
        float acc0[4], acc1[4];
        #pragma unroll
        for (int r = 0; r < 4; r++) { acc0[r] = bb[l]; acc1[r] = bb[l + 32]; }
        #pragma unroll 4
        for (int k4 = 0; k4 < 64; k4++) {
            float4 wa = ((const float4*)w0p)[k4];
            float4 wb = ((const float4*)w1p)[k4];
            #pragma unroll
            for (int r = 0; r < 4; r++) {
                float4 xv = ((const float4*)(xw + r * 256))[k4];
                acc0[r] = fmaf(xv.x, wa.x, acc0[r]);
                acc0[r] = fmaf(xv.y, wa.y, acc0[r]);
                acc0[r] = fmaf(xv.z, wa.z, acc0[r]);
                acc0[r] = fmaf(xv.w, wa.w, acc0[r]);
                acc1[r] = fmaf(xv.x, wb.x, acc1[r]);
                acc1[r] = fmaf(xv.y, wb.y, acc1[r]);
                acc1[r] = fmaf(xv.z, wb.z, acc1[r]);
                acc1[r] = fmaf(xv.w, wb.w, acc1[r]);
            }
        }
        #pragma unroll
        for (int r = 0; r < 4; r++) {
            float a0 = fmaxf(acc0[r], 0.f), a1 = fmaxf(acc1[r], 0.f);
            size_t row = row0 + r;
            g_hb[0][row * 64 + l]      = a0;
            g_hb[0][row * 64 + l + 32] = a1;
            g_seq[row * 256 + l]       = a0;
            g_seq[row * 256 + l + 32]  = a1;
        }
        __syncwarp();
    }
}

// ================= fused gather-propagate + token linear (staged, high-MLP) =================
// warp per node: p = dinv[n]*(dinv[n]*h[n] + sum dinv[s]*h[s]); token = relu(p @ W^T + b)
__global__ void k_prop(int inb, int outb, const float* __restrict__ W,
                       const float* __restrict__ b, int slot) {
    __shared__ float Wt[4096];       // Wt[k*64+j] = W[j*64+k]
    __shared__ float bb[64];
    __shared__ float pbuf[8 * 64];
    __shared__ int2  ebuf[8][32];    // per-warp CSR staging
    int tid = threadIdx.x;
    for (int i = tid; i < 4096; i += 256) {
        int k = i >> 6, j = i & 63;
        Wt[i] = W[j * 64 + k];
    }
    if (tid < 64) bb[tid] = b[tid];
    __syncthreads();
    int warp = tid >> 5, l = tid & 31;
    float* pw = pbuf + warp * 64;
    int2* eb = ebuf[warp];
    const float* hin = g_hb[inb];
    float* hout = g_hb[outb];
    for (int n = blockIdx.x * 8 + warp; n < Nn; n += gridDim.x * 8) {
        int beg = g_off[n], cnt = g_cnt[n];
        float dn = g_dinv[n];
        float2 hv = ((const float2*)(hin + (size_t)n * 64))[l];
        float a0 = dn * hv.x, a1 = dn * hv.y;
        for (int chunk = 0; chunk < cnt; chunk += 32) {
            if (chunk + l < cnt) eb[l] = __ldg(&g_csr[beg + chunk + l]);
            __syncwarp();
            int m = min(32, cnt - chunk);
            int i = 0;
            for (; i + 4 <= m; i += 4) {
                int2 e0 = eb[i], e1 = eb[i+1], e2 = eb[i+2], e3 = eb[i+3];
                float2 v0 = __ldg((const float2*)(hin + (size_t)e0.x * 64) + l);
                float2 v1 = __ldg((const float2*)(hin + (size_t)e1.x * 64) + l);
                float2 v2 = __ldg((const float2*)(hin + (size_t)e2.x * 64) + l);
                float2 v3 = __ldg((const float2*)(hin + (size_t)e3.x * 64) + l);
                float w0 = __int_as_float(e0.y), w1 = __int_as_float(e1.y);
                float w2 = __int_as_float(e2.y), w3 = __int_as_float(e3.y);
                a0 = fmaf(w0, v0.x, a0); a1 = fmaf(w0, v0.y, a1);
                a0 = fmaf(w1, v1.x, a0); a1 = fmaf(w1, v1.y, a1);
                a0 = fmaf(w2, v2.x, a0); a1 = fmaf(w2, v2.y, a1);
                a0 = fmaf(w3, v3.x, a0); a1 = fmaf(w3, v3.y, a1);
            }
            for (; i < m; i++) {
                int2 e0 = eb[i];
                float2 v0 = __ldg((const float2*)(hin + (size_t)e0.x * 64) + l);
                float w0 = __int_as_float(e0.y);
                a0 = fmaf(w0, v0.x, a0); a1 = fmaf(w0, v0.y, a1);
            }
            __syncwarp();
        }
        a0 *= dn; a1 *= dn;
        ((float2*)(hout + (size_t)n * 64))[l] = make_float2(a0, a1);
        ((float2*)pw)[l] = make_float2(a0, a1);
        __syncwarp();
        // token GEMV
        float t0 = bb[l], t1 = bb[l + 32];
        #pragma unroll 4
        for (int k4 = 0; k4 < 16; k4++) {
            float4 xv = ((const float4*)pw)[k4];
            const float* wr = Wt + k4 * 256;
            t0 = fmaf(xv.x, wr[l], t0);        t1 = fmaf(xv.x, wr[l + 32], t1);
            t0 = fmaf(xv.y, wr[64 + l], t0);   t1 = fmaf(xv.y, wr[96 + l], t1);
            t0 = fmaf(xv.z, wr[128 + l], t0);  t1 = fmaf(xv.z, wr[160 + l], t1);
            t0 = fmaf(xv.w, wr[192 + l], t0);  t1 = fmaf(xv.w, wr[224 + l], t1);
        }
        float* op = g_seq + (size_t)n * 256 + slot * 64;
        op[l]      = fmaxf(t0, 0.f);
        op[l + 32] = fmaxf(t1, 0.f);
        __syncwarp();
    }
}

// ================= precompute folded attention matrices =================
__global__ void k_pre(const float* __restrict__ inW, const float* __restrict__ inb,
                      const float* __restrict__ WoutG, const float* __restrict__ boutG) {
    int e = blockIdx.x * blockDim.x + threadIdx.x;
    if (e < 4096) {
        int bcol = e >> 6, a = e & 63;
        float m = 0.f, wv = 0.f;
        for (int j = 0; j < 64; j++) {
            m  = fmaf(__ldg(inW + j * 64 + a),   __ldg(inW + (64 + j) * 64 + bcol), m);
            wv = fmaf(__ldg(WoutG + a * 64 + j), __ldg(inW + (128 + j) * 64 + bcol), wv);
        }
        g_Mt[e] = m;
        g_Wvo[e] = wv;
    }
    if (e < 64) {
        float p = 0.f;
        for (int j = 0; j < 64; j++) p = fmaf(__ldg(inb + j), __ldg(inW + (64 + j) * 64 + e), p);
        g_p2[e] = p;
    } else if (e < 128) {
        int a = e - 64;
        float bv = __ldg(boutG + a);
        for (int j = 0; j < 64; j++) bv = fmaf(__ldg(WoutG + a * 64 + j), __ldg(inb + 128 + j), bv);
        g_bvo[a] = bv;
    }
}

// ================= fused transformer + mean + classifier (R5 proven, 16 warps) =================
#define SSTR 68
#define FSTR 136
#define WSCR 1168

__global__ void __launch_bounds__(512, 1) k_former(
    const float* __restrict__ W1_g,   const float* __restrict__ b1_g,
    const float* __restrict__ W2_g,   const float* __restrict__ b2_g,
    const float* __restrict__ ln1w_g, const float* __restrict__ ln1b_g,
    const float* __restrict__ ln2w_g, const float* __restrict__ ln2b_g,
    const float* __restrict__ Wcls_g, const float* __restrict__ bcls_g,
    float* __restrict__ out)
{
    extern __shared__ float sm[];
    float* MtS   = sm;
    float* WvoS  = MtS + 4096;
    float* W1S   = WvoS + 4096;
    float* W2S   = W1S + 8192;
    float* WclsS = W2S + 8192;
    float* p2S   = WclsS + 2560;
    float* bvoS  = p2S + 64;
    float* b1S   = bvoS + 64;
    float* b2S   = b1S + 128;
    float* bclsS = b2S + 64;
    float* ln1wS = bclsS + 40;
    float* ln1bS = ln1wS + 64;
    float* ln2wS = ln1bS + 64;
    float* ln2bS = ln2wS + 64;
    float* scratch = ln2bS + 64;    // 16 * WSCR

    int tid = threadIdx.x;
    for (int i = tid; i < 4096; i += 512) { MtS[i] = g_Mt[i]; WvoS[i] = g_Wvo[i]; }
    for (int i = tid; i < 8192; i += 512) { int j = i & 127, k = i >> 7; W1S[k * 128 + j] = W1_g[j * 64 + k]; }
    for (int i = tid; i < 8192; i += 512) { int j = i & 63,  k = i >> 6; W2S[k * 64 + j]  = W2_g[j * 128 + k]; }
    for (int i = tid; i < 2560; i += 512) { int j = i % 40,  k = i / 40; WclsS[k * 40 + j] = Wcls_g[j * 64 + k]; }
    if (tid < 64) {
        p2S[tid] = g_p2[tid]; bvoS[tid] = g_bvo[tid]; b2S[tid] = b2_g[tid];
        ln1wS[tid] = ln1w_g[tid]; ln1bS[tid] = ln1b_g[tid];
        ln2wS[tid] = ln2w_g[tid]; ln2bS[tid] = ln2b_g[tid];
    }
    if (tid >= 64 && tid < 192) b1S[tid - 64] = b1_g[tid - 64];
    if (tid >= 192 && tid < 232) bclsS[tid - 192] = bcls_g[tid - 192];
    __syncthreads();

    int warp = tid >> 5, l = tid & 31;
    float* s   = scratch + warp * WSCR;
    float* z   = s + 272;
    float* b2f = z + 272;
    float* sc  = b2f + 544;
    float* hb  = sc + 16;
    const int t = l >> 3, g = l & 7;
    float* srow = s + t * SSTR;
    const int c1 = 4 * g, c2 = 32 + 4 * g;

    for (int n = blockIdx.x * 16 + warp; n < Nn; n += gridDim.x * 16) {
        {
            const float4* sp = (const float4*)(g_seq + (size_t)n * 256);
            int t0 = l >> 4, m = l & 15;
            float4 v0 = sp[l], v1 = sp[l + 32];
            ((float4*)(s + t0 * SSTR))[m] = v0;
            ((float4*)(s + (t0 + 2) * SSTR))[m] = v1;
        }
        __syncwarp();

        // ---- z_t = M s_t ----
        {
            float4 a0 = make_float4(0.f,0.f,0.f,0.f), a1 = a0;
            #pragma unroll 4
            for (int k4 = 0; k4 < 16; k4++) {
                float4 xv = ((const float4*)srow)[k4];
                #pragma unroll
                for (int kk = 0; kk < 4; kk++) {
                    const float* wrow = MtS + (k4 * 4 + kk) * 64;
                    float4 wA = *(const float4*)(wrow + c1);
                    float4 wB = *(const float4*)(wrow + c2);
                    float xk = kk == 0 ? xv.x : kk == 1 ? xv.y : kk == 2 ? xv.z : xv.w;
                    a0.x = fmaf(xk, wA.x, a0.x); a0.y = fmaf(xk, wA.y, a0.y);
                    a0.z = fmaf(xk, wA.z, a0.z); a0.w = fmaf(xk, wA.w, a0.w);
                    a1.x = fmaf(xk, wB.x, a1.x); a1.y = fmaf(xk, wB.y, a1.y);
                    a1.z = fmaf(xk, wB.z, a1.z); a1.w = fmaf(xk, wB.w, a1.w);
                }
            }
            *(float4*)(z + t * SSTR + c1) = a0;
            *(float4*)(z + t * SSTR + c2) = a1;
        }
        __syncwarp();

        // ---- scores + softmax ----
        if (l < 16) {
            int ss = l >> 2, tt = l & 3;
            const float4* ap = (const float4*)(s + ss * SSTR);
            const float4* zp = (const float4*)(z + tt * SSTR);
            const float4* bp = (const float4*)(s + tt * SSTR);
            const float4* pp = (const float4*)p2S;
            float d = 0.f;
            #pragma unroll 4
            for (int k4 = 0; k4 < 16; k4++) {
                float4 a = ap[k4], zz = zp[k4], bq = bp[k4], p = pp[k4];
                d += a.x * zz.x + a.y * zz.y + a.z * zz.z + a.w * zz.w;
                d += p.x * bq.x + p.y * bq.y + p.z * bq.z + p.w * bq.w;
            }
            sc[l] = d * 0.125f;
        }
        __syncwarp();
        if (l < 4) {
            float s0 = sc[l*4], s1 = sc[l*4+1], s2 = sc[l*4+2], s3 = sc[l*4+3];
            float m = fmaxf(fmaxf(s0, s1), fmaxf(s2, s3));
            float e0 = __expf(s0 - m), e1 = __expf(s1 - m), e2 = __expf(s2 - m), e3 = __expf(s3 - m);
            float inv = 1.f / (e0 + e1 + e2 + e3);
            sc[l*4] = e0*inv; sc[l*4+1] = e1*inv; sc[l*4+2] = e2*inv; sc[l*4+3] = e3*inv;
        }
        __syncwarp();

        // ---- m_t = sum_c P[t,c] s_c ----
        {
            float w0 = sc[t*4], w1 = sc[t*4+1], w2 = sc[t*4+2], w3 = sc[t*4+3];
            #pragma unroll
            for (int h = 0; h < 2; h++) {
                int c = h == 0 ? c1 : c2;
                float4 s0 = *(const float4*)(s + c);
                float4 s1 = *(const float4*)(s + SSTR + c);
                float4 s2 = *(const float4*)(s + 2 * SSTR + c);
                float4 s3 = *(const float4*)(s + 3 * SSTR + c);
                float4 r;
                r.x = w0*s0.x + w1*s1.x + w2*s2.x + w3*s3.x;
                r.y = w0*s0.y + w1*s1.y + w2*s2.y + w3*s3.y;
                r.z = w0*s0.z + w1*s1.z + w2*s2.z + w3*s3.z;
                r.w = w0*s0.w + w1*s1.w + w2*s2.w + w3*s3.w;
                *(float4*)(b2f + t * FSTR + c) = r;
            }
        }
        __syncwarp();

        // ---- out = Wvo m + bvo, residual, LN1 ----
        {
            float4 r0 = *(const float4*)(bvoS + c1);
            float4 r1 = *(const float4*)(bvoS + c2);
            const float* arow = b2f + t * FSTR;
            #pragma unroll 4
            for (int k4 = 0; k4 < 16; k4++) {
                float4 av = ((const float4*)arow)[k4];
                #pragma unroll
                for (int kk = 0; kk < 4; kk++) {
                    const float* wrow = WvoS + (k4 * 4 + kk) * 64;
                    float4 wA = *(const float4*)(wrow + c1);
                    float4 wB = *(const float4*)(wrow + c2);
                    float ak = kk == 0 ? av.x : kk == 1 ? av.y : kk == 2 ? av.z : av.w;
                    r0.x = fmaf(ak, wA.x, r0.x); r0.y = fmaf(ak, wA.y, r0.y);
                    r0.z = fmaf(ak, wA.z, r0.z); r0.w = fmaf(ak, wA.w, r0.w);
                    r1.x = fmaf(ak, wB.x, r1.x); r1.y = fmaf(ak, wB.y, r1.y);
                    r1.z = fmaf(ak, wB.z, r1.z); r1.w = fmaf(ak, wB.w, r1.w);
                }
            }
            float4 rs0 = *(const float4*)(srow + c1);
            float4 rs1 = *(const float4*)(srow + c2);
            r0.x += rs0.x; r0.y += rs0.y; r0.z += rs0.z; r0.w += rs0.w;
            r1.x += rs1.x; r1.y += rs1.y; r1.z += rs1.z; r1.w += rs1.w;
            float sum = r0.x + r0.y + r0.z + r0.w + r1.x + r1.y + r1.z + r1.w;
            sum += __shfl_xor_sync(0xffffffffu, sum, 1);
            sum += __shfl_xor_sync(0xffffffffu, sum, 2);
            sum += __shfl_xor_sync(0xffffffffu, sum, 4);
            float mean = sum * 0.015625f;
            float d0 = r0.x-mean, d1 = r0.y-mean, d2 = r0.z-mean, d3 = r0.w-mean;
            float d4 = r1.x-mean, d5 = r1.y-mean, d6 = r1.z-mean, d7 = r1.w-mean;
            float sq = d0*d0 + d1*d1 + d2*d2 + d3*d3 + d4*d4 + d5*d5 + d6*d6 + d7*d7;
            sq += __shfl_xor_sync(0xffffffffu, sq, 1);
            sq += __shfl_xor_sync(0xffffffffu, sq, 2);
            sq += __shfl_xor_sync(0xffffffffu, sq, 4);
            float inv = rsqrtf(sq * 0.015625f + 1e-5f);
            float4 wA = *(const float4*)(ln1wS + c1), wB = *(const float4*)(ln1wS + c2);
            float4 bA = *(const float4*)(ln1bS + c1), bB = *(const float4*)(ln1bS + c2);
            float4 o0, o1;
            o0.x = d0*inv*wA.x + bA.x; o0.y = d1*inv*wA.y + bA.y;
            o0.z = d2*inv*wA.z + bA.z; o0.w = d3*inv*wA.w + bA.w;
            o1.x = d4*inv*wB.x + bB.x; o1.y = d5*inv*wB.y + bB.y;
            o1.z = d6*inv*wB.z + bB.z; o1.w = d7*inv*wB.w + bB.w;
            *(float4*)(srow + c1) = o0;
            *(float4*)(srow + c2) = o1;
        }
        __syncwarp();

        // ---- FF1 + exact gelu ----
        {
            float4 ga[4];
            #pragma unroll
            for (int i = 0; i < 4; i++) ga[i] = *(const float4*)(b1S + 32 * i + c1);
            #pragma unroll 2
            for (int k4 = 0; k4 < 16; k4++) {
                float4 xv = ((const float4*)srow)[k4];
                #pragma unroll
                for (int kk = 0; kk < 4; kk++) {
                    const float* wrow = W1S + (k4 * 4 + kk) * 128;
                    float xk = kk == 0 ? xv.x : kk == 1 ? xv.y : kk == 2 ? xv.z : xv.w;
                    #pragma unroll
                    for (int i = 0; i < 4; i++) {
                        float4 w = *(const float4*)(wrow + 32 * i + c1);
                        ga[i].x = fmaf(xk, w.x, ga[i].x); ga[i].y = fmaf(xk, w.y, ga[i].y);
                        ga[i].z = fmaf(xk, w.z, ga[i].z); ga[i].w = fmaf(xk, w.w, ga[i].w);
                    }
                }
            }
            float* gp = b2f + t * FSTR;
            #pragma unroll
            for (int i = 0; i < 4; i++) {
                float4 v = ga[i];
                v.x = 0.5f * v.x * (1.0f + erff(v.x * 0.70710678118f));
                v.y = 0.5f * v.y * (1.0f + erff(v.y * 0.70710678118f));
                v.z = 0.5f * v.z * (1.0f + erff(v.z * 0.70710678118f));
                v.w = 0.5f * v.w * (1.0f + erff(v.w * 0.70710678118f));
                *(float4*)(gp + 32 * i + c1) = v;
            }
        }
        __syncwarp();

        // ---- FF2 + residual + LN2 + token mean ----
        {
            float4 f0 = *(const float4*)(b2S + c1);
            float4 f1 = *(const float4*)(b2S + c2);
            const float* grow = b2f + t * FSTR;
            #pragma unroll 2
            for (int k4 = 0; k4 < 32; k4++) {
                float4 gv = ((const float4*)grow)[k4];
                #pragma unroll
                for (int kk = 0; kk < 4; kk++) {
                    const float* wrow = W2S + (k4 * 4 + kk) * 64;
                    float4 wA = *(const float4*)(wrow + c1);
                    float4 wB = *(const float4*)(wrow + c2);
                    float gk = kk == 0 ? gv.x : kk == 1 ? gv.y : kk == 2 ? gv.z : gv.w;
                    f0.x = fmaf(gk, wA.x, f0.x); f0.y = fmaf(gk, wA.y, f0.y);
                    f0.z = fmaf(gk, wA.z, f0.z); f0.w = fmaf(gk, wA.w, f0.w);
                    f1.x = fmaf(gk, wB.x, f1.x); f1.y = fmaf(gk, wB.y, f1.y);
                    f1.z = fmaf(gk, wB.z, f1.z); f1.w = fmaf(gk, wB.w, f1.w);
                }
            }
            float4 rs0 = *(const float4*)(srow + c1);
            float4 rs1 = *(const float4*)(srow + c2);
            f0.x += rs0.x; f0.y += rs0.y; f0.z += rs0.z; f0.w += rs0.w;
            f1.x += rs1.x; f1.y += rs1.y; f1.z += rs1.z; f1.w += rs1.w;
            float sum = f0.x + f0.y + f0.z + f0.w + f1.x + f1.y + f1.z + f1.w;
            sum += __shfl_xor_sync(0xffffffffu, sum, 1);
            sum += __shfl_xor_sync(0xffffffffu, sum, 2);
            sum += __shfl_xor_sync(0xffffffffu, sum, 4);
            float mean = sum * 0.015625f;
            float d0 = f0.x-mean, d1 = f0.y-mean, d2 = f0.z-mean, d3 = f0.w-mean;
            float d4 = f1.x-mean, d5 = f1.y-mean, d6 = f1.z-mean, d7 = f1.w-mean;
            float sq = d0*d0 + d1*d1 + d2*d2 + d3*d3 + d4*d4 + d5*d5 + d6*d6 + d7*d7;
            sq += __shfl_xor_sync(0xffffffffu, sq, 1);
            sq += __shfl_xor_sync(0xffffffffu, sq, 2);
            sq += __shfl_xor_sync(0xffffffffu, sq, 4);
            float inv = rsqrtf(sq * 0.015625f + 1e-5f);
            float4 wA = *(const float4*)(ln2wS + c1), wB = *(const float4*)(ln2wS + c2);
            float4 bA = *(const float4*)(ln2bS + c1), bB = *(const float4*)(ln2bS + c2);
            float x2[8];
            x2[0] = d0*inv*wA.x + bA.x; x2[1] = d1*inv*wA.y + bA.y;
            x2[2] = d2*inv*wA.z + bA.z; x2[3] = d3*inv*wA.w + bA.w;
            x2[4] = d4*inv*wB.x + bB.x; x2[5] = d5*inv*wB.y + bB.y;
            x2[6] = d6*inv*wB.z + bB.z; x2[7] = d7*inv*wB.w + bB.w;
            #pragma unroll
            for (int i = 0; i < 8; i++) {
                float v = x2[i];
                v += __shfl_xor_sync(0xffffffffu, v, 8);
                v += __shfl_xor_sync(0xffffffffu, v, 16);
                x2[i] = v * 0.25f;
            }
            if (t == 0) {
                *(float4*)(hb + c1) = make_float4(x2[0], x2[1], x2[2], x2[3]);
                *(float4*)(hb + c2) = make_float4(x2[4], x2[5], x2[6], x2[7]);
            }
        }
        __syncwarp();

        // ---- classifier ----
        {
            float o0 = bclsS[l];
            float o1 = bclsS[32 + g];
            #pragma unroll 4
            for (int k4 = 0; k4 < 16; k4++) {
                float4 hv = ((const float4*)hb)[k4];
                const float* wr = WclsS + k4 * 160;
                o0 = fmaf(hv.x, wr[l], o0);        o1 = fmaf(hv.x, wr[32 + g], o1);
                o0 = fmaf(hv.y, wr[40 + l], o0);   o1 = fmaf(hv.y, wr[72 + g], o1);
                o0 = fmaf(hv.z, wr[80 + l], o0);   o1 = fmaf(hv.z, wr[112 + g], o1);
                o0 = fmaf(hv.w, wr[120 + l], o0);  o1 = fmaf(hv.w, wr[152 + g], o1);
            }
            out[(size_t)n * 40 + l] = o0;
            if (l < 8) out[(size_t)n * 40 + 32 + l] = o1;
        }
        __syncwarp();
    }
}

extern "C" void kernel_launch(void* const* d_in, const int* in_sizes, int n_in,
                              void* d_out, int out_size) {
    const float* x     = (const float*)d_in[0];
    const int*   ei    = (const int*)d_in[1];
    const float* W_in  = (const float*)d_in[2];
    const float* b_in  = (const float*)d_in[3];
    const float* sg_W  = (const float*)d_in[4];
    const float* sg_b  = (const float*)d_in[5];
    const float* inW   = (const float*)d_in[6];
    const float* inb   = (const float*)d_in[7];
    const float* Wout  = (const float*)d_in[8];
    const float* bout  = (const float*)d_in[9];
    const float* W1    = (const float*)d_in[10];
    const float* b1    = (const float*)d_in[11];
    const float* W2    = (const float*)d_in[12];
    const float* b2    = (const float*)d_in[13];
    const float* ln1w  = (const float*)d_in[14];
    const float* ln1b  = (const float*)d_in[15];
    const float* ln2w  = (const float*)d_in[16];
    const float* ln2b  = (const float*)d_in[17];
    const float* Wcls  = (const float*)d_in[18];
    const float* bcls  = (const float*)d_in[19];
    float* out = (float*)d_out;

    // former smem: 27752 weights + 16*1168 scratch = 46440 floats = 185760 B
    cudaFuncSetAttribute(k_in_linear, cudaFuncAttributeMaxDynamicSharedMemorySize, 99584);
    cudaFuncSetAttribute(k_former,    cudaFuncAttributeMaxDynamicSharedMemorySize, 185760);

    // CSR build + dinv
    k_init<<<(Nn + 255) / 256, 256>>>();
    k_count<<<(Ee + 255) / 256, 256>>>(ei + Ee);
    k_scan1<<<NB_SCAN, 1024>>>();
    k_scan2<<<1, 1>>>();
    k_scan3<<<NB_SCAN, 1024>>>();
    k_fill<<<(Ee + 255) / 256, 256>>>(ei, ei + Ee);

    // h0 + seq slot 0
    k_in_linear<<<592, 256, 99584>>>(x, W_in, b_in);

    // folded attention matrices
    k_pre<<<16, 256>>>(inW, inb, Wout, bout);

    // 3 hops: staged gather + fused token GEMV
    const int ib[3] = {0, 1, 2};
    const int ob[3] = {1, 2, 1};
    for (int hop = 0; hop < 3; hop++) {
        k_prop<<<1184, 256>>>(ib[hop], ob[hop], sg_W + hop * 4096, sg_b + hop * 64, hop + 1);
    }

    // fused transformer + pooling + classifier — single wave, 16 warps/CTA
    k_former<<<148, 512, 185760>>>(W1, b1, W2, b2, ln1w, ln1b, ln2w, ln2b, Wcls, bcls, out);
}

// round 7
// speedup vs baseline: 2.1621x; 1.0000x over previous
#include <cuda_runtime.h>
#include <math.h>

#define Nn   100000
#define Ee   1600000
#define NH   (Nn * 64)
#define NB_SCAN 98

typedef unsigned long long ull;
__device__ __forceinline__ ull bcast2(float x) {
    ull r; asm("mov.b64 %0, {%1, %1};" : "=l"(r) : "f"(x)); return r;
}
__device__ __forceinline__ void ffma2(ull& d, ull a, ull b) {
    asm("fma.rn.f32x2 %0, %1, %2, %0;" : "+l"(d) : "l"(a), "l"(b));
}
__device__ __forceinline__ float2 unpk(ull v) {
    float2 f; asm("mov.b64 {%0, %1}, %2;" : "=f"(f.x), "=f"(f.y) : "l"(v)); return f;
}

// ---- persistent device scratch ----
__device__ float g_dinv[Nn];
__device__ int   g_cnt[Nn];
__device__ int   g_off[Nn];
__device__ int   g_cur[Nn];
__device__ int   g_bsum[128];
__device__ int2  g_csr[Ee];
__device__ float g_hb[3][NH];
__device__ float g_seq[(size_t)Nn * 256];
__device__ float g_Mt[4096];
__device__ float g_Wvo[4096];
__device__ float g_p2[64];
__device__ float g_bvo[64];

// ================= CSR build + dinv =================
__global__ void k_init() {
    int i = blockIdx.x * blockDim.x + threadIdx.x;
    if (i < Nn) g_cnt[i] = 0;
}
__global__ void k_count(const int* __restrict__ dst) {
    int e = blockIdx.x * blockDim.x + threadIdx.x;
    if (e < Ee) atomicAdd(&g_cnt[dst[e]], 1);
}
__global__ void k_scan1() {
    __shared__ int smv[1024];
    int i = blockIdx.x * 1024 + threadIdx.x;
    int v = (i < Nn) ? g_cnt[i] : 0;
    smv[threadIdx.x] = v;
    __syncthreads();
    for (int off = 1; off < 1024; off <<= 1) {
        int t = 0;
        if (threadIdx.x >= off) t = smv[threadIdx.x - off];
        __syncthreads();
        if (threadIdx.x >= off) smv[threadIdx.x] += t;
        __syncthreads();
    }
    if (i < Nn) g_off[i] = smv[threadIdx.x];
    if (threadIdx.x == 1023) g_bsum[blockIdx.x] = smv[1023];
}
__global__ void k_scan2() {
    int acc = 0;
    for (int b = 0; b < NB_SCAN; b++) { int t = g_bsum[b]; g_bsum[b] = acc; acc += t; }
}
__global__ void k_scan3() {
    int i = blockIdx.x * 1024 + threadIdx.x;
    if (i < Nn) {
        int incl = g_off[i] + g_bsum[i >> 10];
        int excl = incl - g_cnt[i];
        g_off[i] = excl;
        g_cur[i] = excl;
        g_dinv[i] = rsqrtf((float)g_cnt[i] + 1.0f);
    }
}
__global__ void k_fill(const int* __restrict__ src, const int* __restrict__ dst) {
    int e = blockIdx.x * blockDim.x + threadIdx.x;
    if (e < Ee) {
        int s = src[e], d = dst[e];
        int pos = atomicAdd(&g_cur[d], 1);
        g_csr[pos] = make_int2(s, __float_as_int(g_dinv[s]));
    }
}

// ================= h0 = relu(x @ W_in^T + b_in) =================
__global__ void k_in_linear(const float* __restrict__ x, const float* __restrict__ W,
                            const float* __restrict__ b) {
    extern __shared__ float sm[];
    float* Ws = sm;                 // [64][260]
    float* bb = Ws + 64 * 260;
    float* xb = bb + 64;
    int tid = threadIdx.x;
    for (int i = tid; i < 64 * 64; i += 256) {
        int j = i >> 6, q = i & 63;
        ((float4*)(Ws + j * 260))[q] = ((const float4*)(W + j * 256))[q];
    }
    if (tid < 64) bb[tid] = b[tid];
    __syncthreads();
    int warp = tid >> 5, l = tid & 31;
    float* xw = xb + warp * 1024;
    const float* w0p = Ws + l * 260;
    const float* w1p = Ws + (l + 32) * 260;
    for (int grp = blockIdx.x * 8 + warp; grp < 25000; grp += gridDim.x * 8) {
        int row0 = grp * 4;
        const float4* xg = (const float4*)(x + (size_t)row0 * 256);
        #pragma unroll
        for (int r = 0; r < 4; r++) {
            ((float4*)xw)[r * 64 + l]      = xg[r * 64 + l];
            ((float4*)xw)[r * 64 + l + 32] = xg[r * 64 + l + 32];
        }
        __syncwarp();
        float acc0[4], acc1[4];
        #pragma unroll
        for (int r = 0; r < 4; r++) { acc0[r] = bb[l]; acc1[r] = bb[l + 32]; }
        #pragma unroll 4
        for (int k4 = 0; k4 < 64; k4++) {
            float4 wa = ((const float4*)w0p)[k4];
            float4 wb = ((const float4*)w1p)[k4];
            #pragma unroll
            for (int r = 0; r < 4; r++) {
                float4 xv = ((const float4*)(xw + r * 256))[k4];
                acc0[r] = fmaf(xv.x, wa.x, acc0[r]);
                acc0[r] = fmaf(xv.y, wa.y, acc0[r]);
                acc0[r] = fmaf(xv.z, wa.z, acc0[r]);
                acc0[r] = fmaf(xv.w, wa.w, acc0[r]);
                acc1[r] = fmaf(xv.x, wb.x, acc1[r]);
                acc1[r] = fmaf(xv.y, wb.y, acc1[r]);
                acc1[r] = fmaf(xv.z, wb.z, acc1[r]);
                acc1[r] = fmaf(xv.w, wb.w, acc1[r]);
            }
        }
        #pragma unroll
        for (int r = 0; r < 4; r++) {
            float a0 = fmaxf(acc0[r], 0.f), a1 = fmaxf(acc1[r], 0.f);
            size_t row = row0 + r;
            g_hb[0][row * 64 + l]      = a0;
            g_hb[0][row * 64 + l + 32] = a1;
            g_seq[row * 256 + l]       = a0;
            g_seq[row * 256 + l + 32]  = a1;
        }
        __syncwarp();
    }
}

// ================= fused gather-propagate + token linear (MLP=8) =================
__global__ void k_prop(int inb, int outb, const float* __restrict__ W,
                       const float* __restrict__ b, int slot) {
    __shared__ float Wt[4096];
    __shared__ float bb[64];
    __shared__ float pbuf[8 * 64];
    __shared__ int2  ebuf[8][32];
    int tid = threadIdx.x;
    for (int i = tid; i < 4096; i += 256) {
        int k = i >> 6, j = i & 63;
        Wt[i] = W[j * 64 + k];
    }
    if (tid < 64) bb[tid] = b[tid];
    __syncthreads();
    int warp = tid >> 5, l = tid & 31;
    float* pw = pbuf + warp * 64;
    int2* eb = ebuf[warp];
    const float* hin = g_hb[inb];
    float* hout = g_hb[outb];
    for (int n = blockIdx.x * 8 + warp; n < Nn; n += gridDim.x * 8) {
        int beg = g_off[n], cnt = g_cnt[n];
        float dn = g_dinv[n];
        float2 hv = ((const float2*)(hin + (size_t)n * 64))[l];
        float a0 = dn * hv.x, a1 = dn * hv.y;
        for (int chunk = 0; chunk < cnt; chunk += 32) {
            if (chunk + l < cnt) eb[l] = __ldg(&g_csr[beg + chunk + l]);
            __syncwarp();
            int m = min(32, cnt - chunk);
            int i = 0;
            for (; i + 8 <= m; i += 8) {
                float2 v[8]; float w[8];
                #pragma unroll
                for (int u = 0; u < 8; u++) {
                    int2 e = eb[i + u];
                    v[u] = __ldg((const float2*)(hin + (size_t)e.x * 64) + l);
                    w[u] = __int_as_float(e.y);
                }
                #pragma unroll
                for (int u = 0; u < 8; u++) {
                    a0 = fmaf(w[u], v[u].x, a0);
                    a1 = fmaf(w[u], v[u].y, a1);
                }
            }
            for (; i + 4 <= m; i += 4) {
                float2 v[4]; float w[4];
                #pragma unroll
                for (int u = 0; u < 4; u++) {
                    int2 e = eb[i + u];
                    v[u] = __ldg((const float2*)(hin + (size_t)e.x * 64) + l);
                    w[u] = __int_as_float(e.y);
                }
                #pragma unroll
                for (int u = 0; u < 4; u++) {
                    a0 = fmaf(w[u], v[u].x, a0);
                    a1 = fmaf(w[u], v[u].y, a1);
                }
            }
            for (; i < m; i++) {
                int2 e = eb[i];
                float2 v0 = __ldg((const float2*)(hin + (size_t)e.x * 64) + l);
                float w0 = __int_as_float(e.y);
                a0 = fmaf(w0, v0.x, a0); a1 = fmaf(w0, v0.y, a1);
            }
            __syncwarp();
        }
        a0 *= dn; a1 *= dn;
        ((float2*)(hout + (size_t)n * 64))[l] = make_float2(a0, a1);
        ((float2*)pw)[l] = make_float2(a0, a1);
        __syncwarp();
        float t0 = bb[l], t1 = bb[l + 32];
        #pragma unroll 4
        for (int k4 = 0; k4 < 16; k4++) {
            float4 xv = ((const float4*)pw)[k4];
            const float* wr = Wt + k4 * 256;
            t0 = fmaf(xv.x, wr[l], t0);        t1 = fmaf(xv.x, wr[l + 32], t1);
            t0 = fmaf(xv.y, wr[64 + l], t0);   t1 = fmaf(xv.y, wr[96 + l], t1);
            t0 = fmaf(xv.z, wr[128 + l], t0);  t1 = fmaf(xv.z, wr[160 + l], t1);
            t0 = fmaf(xv.w, wr[192 + l], t0);  t1 = fmaf(xv.w, wr[224 + l], t1);
        }
        float* op = g_seq + (size_t)n * 256 + slot * 64;
        op[l]      = fmaxf(t0, 0.f);
        op[l + 32] = fmaxf(t1, 0.f);
        __syncwarp();
    }
}

// ================= precompute folded attention matrices =================
__global__ void k_pre(const float* __restrict__ inW, const float* __restrict__ inb,
                      const float* __restrict__ WoutG, const float* __restrict__ boutG) {
    int e = blockIdx.x * blockDim.x + threadIdx.x;
    if (e < 4096) {
        int bcol = e >> 6, a = e & 63;
        float m = 0.f, wv = 0.f;
        for (int j = 0; j < 64; j++) {
            m  = fmaf(__ldg(inW + j * 64 + a),   __ldg(inW + (64 + j) * 64 + bcol), m);
            wv = fmaf(__ldg(WoutG + a * 64 + j), __ldg(inW + (128 + j) * 64 + bcol), wv);
        }
        g_Mt[e] = m;
        g_Wvo[e] = wv;
    }
    if (e < 64) {
        float p = 0.f;
        for (int j = 0; j < 64; j++) p = fmaf(__ldg(inb + j), __ldg(inW + (64 + j) * 64 + e), p);
        g_p2[e] = p;
    } else if (e < 128) {
        int a = e - 64;
        float bv = __ldg(boutG + a);
        for (int j = 0; j < 64; j++) bv = fmaf(__ldg(WoutG + a * 64 + j), __ldg(inb + 128 + j), bv);
        g_bvo[a] = bv;
    }
}

// ================= fused transformer + mean + classifier (f32x2 GEMVs) =================
#define SSTR 68
#define FSTR 136
#define WSCR 1168

__global__ void __launch_bounds__(512, 1) k_former(
    const float* __restrict__ W1_g,   const float* __restrict__ b1_g,
    const float* __restrict__ W2_g,   const float* __restrict__ b2_g,
    const float* __restrict__ ln1w_g, const float* __restrict__ ln1b_g,
    const float* __restrict__ ln2w_g, const float* __restrict__ ln2b_g,
    const float* __restrict__ Wcls_g, const float* __restrict__ bcls_g,
    float* __restrict__ out)
{
    extern __shared__ float sm[];
    float* MtS   = sm;
    float* WvoS  = MtS + 4096;
    float* W1S   = WvoS + 4096;
    float* W2S   = W1S + 8192;
    float* WclsS = W2S + 8192;
    float* p2S   = WclsS + 2560;
    float* bvoS  = p2S + 64;
    float* b1S   = bvoS + 64;
    float* b2S   = b1S + 128;
    float* bclsS = b2S + 64;
    float* ln1wS = bclsS + 40;
    float* ln1bS = ln1wS + 64;
    float* ln2wS = ln1bS + 64;
    float* ln2bS = ln2wS + 64;
    float* scratch = ln2bS + 64;

    int tid = threadIdx.x;
    for (int i = tid; i < 4096; i += 512) { MtS[i] = g_Mt[i]; WvoS[i] = g_Wvo[i]; }
    for (int i = tid; i < 8192; i += 512) { int j = i & 127, k = i >> 7; W1S[k * 128 + j] = W1_g[j * 64 + k]; }
    for (int i = tid; i < 8192; i += 512) { int j = i & 63,  k = i >> 6; W2S[k * 64 + j]  = W2_g[j * 128 + k]; }
    for (int i = tid; i < 2560; i += 512) { int j = i % 40,  k = i / 40; WclsS[k * 40 + j] = Wcls_g[j * 64 + k]; }
    if (tid < 64) {
        p2S[tid] = g_p2[tid]; bvoS[tid] = g_bvo[tid]; b2S[tid] = b2_g[tid];
        ln1wS[tid] = ln1w_g[tid]; ln1bS[tid] = ln1b_g[tid];
        ln2wS[tid] = ln2w_g[tid]; ln2bS[tid] = ln2b_g[tid];
    }
    if (tid >= 64 && tid < 192) b1S[tid - 64] = b1_g[tid - 64];
    if (tid >= 192 && tid < 232) bclsS[tid - 192] = bcls_g[tid - 192];
    __syncthreads();

    int warp = tid >> 5, l = tid & 31;
    float* s   = scratch + warp * WSCR;
    float* z   = s + 272;
    float* b2f = z + 272;
    float* sc  = b2f + 544;
    float* hb  = sc + 16;
    const int t = l >> 3, g = l & 7;
    float* srow = s + t * SSTR;
    const int c1 = 4 * g, c2 = 32 + 4 * g;

    for (int n = blockIdx.x * 16 + warp; n < Nn; n += gridDim.x * 16) {
        {
            const float4* sp = (const float4*)(g_seq + (size_t)n * 256);
            int t0 = l >> 4, m = l & 15;
            float4 v0 = sp[l], v1 = sp[l + 32];
            ((float4*)(s + t0 * SSTR))[m] = v0;
            ((float4*)(s + (t0 + 2) * SSTR))[m] = v1;
        }
        __syncwarp();

        // ---- z_t = M s_t (f32x2) ----
        {
            ull p0 = 0, p1 = 0, p2 = 0, p3 = 0;
            #pragma unroll 4
            for (int k4 = 0; k4 < 16; k4++) {
                float4 xv = ((const float4*)srow)[k4];
                #pragma unroll
                for (int kk = 0; kk < 4; kk++) {
                    const float* wrow = MtS + (k4 * 4 + kk) * 64;
                    ulonglong2 wa = *(const ulonglong2*)(wrow + c1);
                    ulonglong2 wb = *(const ulonglong2*)(wrow + c2);
                    float xk = kk == 0 ? xv.x : kk == 1 ? xv.y : kk == 2 ? xv.z : xv.w;
                    ull x2 = bcast2(xk);
                    ffma2(p0, x2, wa.x); ffma2(p1, x2, wa.y);
                    ffma2(p2, x2, wb.x); ffma2(p3, x2, wb.y);
                }
            }
            *(ulonglong2*)(z + t * SSTR + c1) = make_ulonglong2(p0, p1);
            *(ulonglong2*)(z + t * SSTR + c2) = make_ulonglong2(p2, p3);
        }
        __syncwarp();

        // ---- scores + softmax ----
        if (l < 16) {
            int ss = l >> 2, tt = l & 3;
            const float4* ap = (const float4*)(s + ss * SSTR);
            const float4* zp = (const float4*)(z + tt * SSTR);
            const float4* bp = (const float4*)(s + tt * SSTR);
            const float4* pp = (const float4*)p2S;
            float d = 0.f;
            #pragma unroll 4
            for (int k4 = 0; k4 < 16; k4++) {
                float4 a = ap[k4], zz = zp[k4], bq = bp[k4], p = pp[k4];
                d += a.x * zz.x + a.y * zz.y + a.z * zz.z + a.w * zz.w;
                d += p.x * bq.x + p.y * bq.y + p.z * bq.z + p.w * bq.w;
            }
            sc[l] = d * 0.125f;
        }
        __syncwarp();
        if (l < 4) {
            float s0 = sc[l*4], s1 = sc[l*4+1], s2 = sc[l*4+2], s3 = sc[l*4+3];
            float m = fmaxf(fmaxf(s0, s1), fmaxf(s2, s3));
            float e0 = __expf(s0 - m), e1 = __expf(s1 - m), e2 = __expf(s2 - m), e3 = __expf(s3 - m);
            float inv = 1.f / (e0 + e1 + e2 + e3);
            sc[l*4] = e0*inv; sc[l*4+1] = e1*inv; sc[l*4+2] = e2*inv; sc[l*4+3] = e3*inv;
        }
        __syncwarp();

        // ---- m_t = sum_c P[t,c] s_c ----
        {
            float w0 = sc[t*4], w1 = sc[t*4+1], w2 = sc[t*4+2], w3 = sc[t*4+3];
            #pragma unroll
            for (int h = 0; h < 2; h++) {
                int c = h == 0 ? c1 : c2;
                float4 s0 = *(const float4*)(s + c);
                float4 s1 = *(const float4*)(s + SSTR + c);
                float4 s2 = *(const float4*)(s + 2 * SSTR + c);
                float4 s3 = *(const float4*)(s + 3 * SSTR + c);
                float4 r;
                r.x = w0*s0.x + w1*s1.x + w2*s2.x + w3*s3.x;
                r.y = w0*s0.y + w1*s1.y + w2*s2.y + w3*s3.y;
                r.z = w0*s0.z + w1*s1.z + w2*s2.z + w3*s3.z;
                r.w = w0*s0.w + w1*s1.w + w2*s2.w + w3*s3.w;
                *(float4*)(b2f + t * FSTR + c) = r;
            }
        }
        __syncwarp();

        // ---- out = Wvo m + bvo, residual, LN1 (f32x2) ----
        {
            ulonglong2 bv1 = *(const ulonglong2*)(bvoS + c1);
            ulonglong2 bv2 = *(const ulonglong2*)(bvoS + c2);
            ull p0 = bv1.x, p1 = bv1.y, p2 = bv2.x, p3 = bv2.y;
            const float* arow = b2f + t * FSTR;
            #pragma unroll 4
            for (int k4 = 0; k4 < 16; k4++) {
                float4 av = ((const float4*)arow)[k4];
                #pragma unroll
                for (int kk = 0; kk < 4; kk++) {
                    const float* wrow = WvoS + (k4 * 4 + kk) * 64;
                    ulonglong2 wa = *(const ulonglong2*)(wrow + c1);
                    ulonglong2 wb = *(const ulonglong2*)(wrow + c2);
                    float ak = kk == 0 ? av.x : kk == 1 ? av.y : kk == 2 ? av.z : av.w;
                    ull a2 = bcast2(ak);
                    ffma2(p0, a2, wa.x); ffma2(p1, a2, wa.y);
                    ffma2(p2, a2, wb.x); ffma2(p3, a2, wb.y);
                }
            }
            float2 q0 = unpk(p0), q1 = unpk(p1), q2 = unpk(p2), q3 = unpk(p3);
            float4 rs0 = *(const float4*)(srow + c1);
            float4 rs1 = *(const float4*)(srow + c2);
            float r[8];
            r[0] = q0.x + rs0.x; r[1] = q0.y + rs0.y; r[2] = q1.x + rs0.z; r[3] = q1.y + rs0.w;
            r[4] = q2.x + rs1.x; r[5] = q2.y + rs1.y; r[6] = q3.x + rs1.z; r[7] = q3.y + rs1.w;
            float sum = r[0]+r[1]+r[2]+r[3]+r[4]+r[5]+r[6]+r[7];
            sum += __shfl_xor_sync(0xffffffffu, sum, 1);
            sum += __shfl_xor_sync(0xffffffffu, sum, 2);
            sum += __shfl_xor_sync(0xffffffffu, sum, 4);
            float mean = sum * 0.015625f;
            float sq = 0.f;
            #pragma unroll
            for (int i = 0; i < 8; i++) { float dd = r[i] - mean; sq = fmaf(dd, dd, sq); }
            sq += __shfl_xor_sync(0xffffffffu, sq, 1);
            sq += __shfl_xor_sync(0xffffffffu, sq, 2);
            sq += __shfl_xor_sync(0xffffffffu, sq, 4);
            float inv = rsqrtf(sq * 0.015625f + 1e-5f);
            float4 wA = *(const float4*)(ln1wS + c1), wB = *(const float4*)(ln1wS + c2);
            float4 bA = *(const float4*)(ln1bS + c1), bB = *(const float4*)(ln1bS + c2);
            float4 o0, o1;
            o0.x = (r[0]-mean)*inv*wA.x + bA.x; o0.y = (r[1]-mean)*inv*wA.y + bA.y;
            o0.z = (r[2]-mean)*inv*wA.z + bA.z; o0.w = (r[3]-mean)*inv*wA.w + bA.w;
            o1.x = (r[4]-mean)*inv*wB.x + bB.x; o1.y = (r[5]-mean)*inv*wB.y + bB.y;
            o1.z = (r[6]-mean)*inv*wB.z + bB.z; o1.w = (r[7]-mean)*inv*wB.w + bB.w;
            *(float4*)(srow + c1) = o0;
            *(float4*)(srow + c2) = o1;
        }
        __syncwarp();

        // ---- FF1 + exact gelu (f32x2) ----
        {
            ull q[8];
            #pragma unroll
            for (int i = 0; i < 4; i++) {
                ulonglong2 bi = *(const ulonglong2*)(b1S + 32 * i + c1);
                q[2*i] = bi.x; q[2*i+1] = bi.y;
            }
            #pragma unroll 2
            for (int k4 = 0; k4 < 16; k4++) {
                float4 xv = ((const float4*)srow)[k4];
                #pragma unroll
                for (int kk = 0; kk < 4; kk++) {
                    const float* wrow = W1S + (k4 * 4 + kk) * 128;
                    float xk = kk == 0 ? xv.x : kk == 1 ? xv.y : kk == 2 ? xv.z : xv.w;
                    ull x2 = bcast2(xk);
                    #pragma unroll
                    for (int i = 0; i < 4; i++) {
                        ulonglong2 w = *(const ulonglong2*)(wrow + 32 * i + c1);
                        ffma2(q[2*i], x2, w.x);
                        ffma2(q[2*i+1], x2, w.y);
                    }
                }
            }
            float* gp = b2f + t * FSTR;
            #pragma unroll
            for (int i = 0; i < 4; i++) {
                float2 u0 = unpk(q[2*i]), u1 = unpk(q[2*i+1]);
                float4 v;
                v.x = 0.5f * u0.x * (1.0f + erff(u0.x * 0.70710678118f));
                v.y = 0.5f * u0.y * (1.0f + erff(u0.y * 0.70710678118f));
                v.z = 0.5f * u1.x * (1.0f + erff(u1.x * 0.70710678118f));
                v.w = 0.5f * u1.y * (1.0f + erff(u1.y * 0.70710678118f));
                *(float4*)(gp + 32 * i + c1) = v;
            }
        }
        __syncwarp();

        // ---- FF2 + residual + LN2 + token mean (f32x2) ----
        {
            ulonglong2 bv1 = *(const ulonglong2*)(b2S + c1);
            ulonglong2 bv2 = *(const ulonglong2*)(b2S + c2);
            ull p0 = bv1.x, p1 = bv1.y, p2 = bv2.x, p3 = bv2.y;
            const float* grow = b2f + t * FSTR;
            #pragma unroll 2
            for (int k4 = 0; k4 < 32; k4++) {
                float4 gv = ((const float4*)grow)[k4];
                #pragma unroll
                for (int kk = 0; kk < 4; kk++) {
                    const float* wrow = W2S + (k4 * 4 + kk) * 64;
                    ulonglong2 wa = *(const ulonglong2*)(wrow + c1);
                    ulonglong2 wb = *(const ulonglong2*)(wrow + c2);
                    float gk = kk == 0 ? gv.x : kk == 1 ? gv.y : kk == 2 ? gv.z : gv.w;
                    ull g2 = bcast2(gk);
                    ffma2(p0, g2, wa.x); ffma2(p1, g2, wa.y);
                    ffma2(p2, g2, wb.x); ffma2(p3, g2, wb.y);
                }
            }
            float2 q0 = unpk(p0), q1 = unpk(p1), q2 = unpk(p2), q3 = unpk(p3);
            float4 rs0 = *(const float4*)(srow + c1);
            float4 rs1 = *(const float4*)(srow + c2);
            float f[8];
            f[0] = q0.x + rs0.x; f[1] = q0.y + rs0.y; f[2] = q1.x + rs0.z; f[3] = q1.y + rs0.w;
            f[4] = q2.x + rs1.x; f[5] = q2.y + rs1.y; f[6] = q3.x + rs1.z; f[7] = q3.y + rs1.w;
            float sum = f[0]+f[1]+f[2]+f[3]+f[4]+f[5]+f[6]+f[7];
            sum += __shfl_xor_sync(0xffffffffu, sum, 1);
            sum += __shfl_xor_sync(0xffffffffu, sum, 2);
            sum += __shfl_xor_sync(0xffffffffu, sum, 4);
            float mean = sum * 0.015625f;
            float sq = 0.f;
            #pragma unroll
            for (int i = 0; i < 8; i++) { float dd = f[i] - mean; sq = fmaf(dd, dd, sq); }
            sq += __shfl_xor_sync(0xffffffffu, sq, 1);
            sq += __shfl_xor_sync(0xffffffffu, sq, 2);
            sq += __shfl_xor_sync(0xffffffffu, sq, 4);
            float inv = rsqrtf(sq * 0.015625f + 1e-5f);
            const float* w2p = ln2wS;
            const float* b2p = ln2bS;
            float x2v[8];
            #pragma unroll
            for (int i = 0; i < 8; i++) {
                int j = (i < 4) ? (c1 + i) : (c2 + i - 4);
                x2v[i] = (f[i] - mean) * inv * w2p[j] + b2p[j];
            }
            #pragma unroll
            for (int i = 0; i < 8; i++) {
                float v = x2v[i];
                v += __shfl_xor_sync(0xffffffffu, v, 8);
                v += __shfl_xor_sync(0xffffffffu, v, 16);
                x2v[i] = v * 0.25f;
            }
            if (t == 0) {
                *(float4*)(hb + c1) = make_float4(x2v[0], x2v[1], x2v[2], x2v[3]);
                *(float4*)(hb + c2) = make_float4(x2v[4], x2v[5], x2v[6], x2v[7]);
            }
        }
        __syncwarp();

        // ---- classifier ----
        {
            float o0 = bclsS[l];
            float o1 = bclsS[32 + g];
            #pragma unroll 4
            for (int k4 = 0; k4 < 16; k4++) {
                float4 hv = ((const float4*)hb)[k4];
                const float* wr = WclsS + k4 * 160;
                o0 = fmaf(hv.x, wr[l], o0);        o1 = fmaf(hv.x, wr[32 + g], o1);
                o0 = fmaf(hv.y, wr[40 + l], o0);   o1 = fmaf(hv.y, wr[72 + g], o1);
                o0 = fmaf(hv.z, wr[80 + l], o0);   o1 = fmaf(hv.z, wr[112 + g], o1);
                o0 = fmaf(hv.w, wr[120 + l], o0);  o1 = fmaf(hv.w, wr[152 + g], o1);
            }
            out[(size_t)n * 40 + l] = o0;
            if (l < 8) out[(size_t)n * 40 + 32 + l] = o1;
        }
        __syncwarp();
    }
}

extern "C" void kernel_launch(void* const* d_in, const int* in_sizes, int n_in,
                              void* d_out, int out_size) {
    const float* x     = (const float*)d_in[0];
    const int*   ei    = (const int*)d_in[1];
    const float* W_in  = (const float*)d_in[2];
    const float* b_in  = (const float*)d_in[3];
    const float* sg_W  = (const float*)d_in[4];
    const float* sg_b  = (const float*)d_in[5];
    const float* inW   = (const float*)d_in[6];
    const float* inb   = (const float*)d_in[7];
    const float* Wout  = (const float*)d_in[8];
    const float* bout  = (const float*)d_in[9];
    const float* W1    = (const float*)d_in[10];
    const float* b1    = (const float*)d_in[11];
    const float* W2    = (const float*)d_in[12];
    const float* b2    = (const float*)d_in[13];
    const float* ln1w  = (const float*)d_in[14];
    const float* ln1b  = (const float*)d_in[15];
    const float* ln2w  = (const float*)d_in[16];
    const float* ln2b  = (const float*)d_in[17];
    const float* Wcls  = (const float*)d_in[18];
    const float* bcls  = (const float*)d_in[19];
    float* out = (float*)d_out;

    cudaFuncSetAttribute(k_in_linear, cudaFuncAttributeMaxDynamicSharedMemorySize, 99584);
    cudaFuncSetAttribute(k_former,    cudaFuncAttributeMaxDynamicSharedMemorySize, 185760);

    k_init<<<(Nn + 255) / 256, 256>>>();
    k_count<<<(Ee + 255) / 256, 256>>>(ei + Ee);
    k_scan1<<<NB_SCAN, 1024>>>();
    k_scan2<<<1, 1>>>();
    k_scan3<<<NB_SCAN, 1024>>>();
    k_fill<<<(Ee + 255) / 256, 256>>>(ei, ei + Ee);

    k_in_linear<<<592, 256, 99584>>>(x, W_in, b_in);
    k_pre<<<16, 256>>>(inW, inb, Wout, bout);

    const int ib[3] = {0, 1, 2};
    const int ob[3] = {1, 2, 1};
    for (int hop = 0; hop < 3; hop++) {
        k_prop<<<1184, 256>>>(ib[hop], ob[hop], sg_W + hop * 4096, sg_b + hop * 64, hop + 1);
    }

    k_former<<<148, 512, 185760>>>(W1, b1, W2, b2, ln1w, ln1b, ln2w, ln2b, Wcls, bcls, out);
}

// round 8
// speedup vs baseline: 2.1869x; 1.0115x over previous
#include <cuda_runtime.h>
#include <math.h>

#define Nn   100000
#define Ee   1600000
#define NH   (Nn * 64)
#define NB_SCAN 98

typedef unsigned long long ull;
__device__ __forceinline__ ull bcast2(float x) {
    ull r; asm("mov.b64 %0, {%1, %1};" : "=l"(r) : "f"(x)); return r;
}
__device__ __forceinline__ void ffma2(ull& d, ull a, ull b) {
    asm("fma.rn.f32x2 %0, %1, %2, %0;" : "+l"(d) : "l"(a), "l"(b));
}
__device__ __forceinline__ float2 unpk(ull v) {
    float2 f; asm("mov.b64 {%0, %1}, %2;" : "=f"(f.x), "=f"(f.y) : "l"(v)); return f;
}

// ---- persistent device scratch ----
__device__ float g_dinv[Nn];
__device__ int   g_cnt[Nn];
__device__ int   g_off[Nn];
__device__ int   g_cur[Nn];
__device__ int   g_bsum[128];
__device__ int2  g_csr[Ee];
__device__ float g_hb[3][NH];
__device__ float g_seq[(size_t)Nn * 256];
__device__ float g_Mt[4096];
__device__ float g_Wvo[4096];
__device__ float g_p2[64];
__device__ float g_bvo[64];

// ================= CSR build + dinv =================
__global__ void k_init() {
    int i = blockIdx.x * blockDim.x + threadIdx.x;
    if (i < Nn) g_cnt[i] = 0;
}
__global__ void k_count(const int* __restrict__ dst) {
    int e = blockIdx.x * blockDim.x + threadIdx.x;
    if (e < Ee) atomicAdd(&g_cnt[dst[e]], 1);
}
__global__ void k_scan1() {
    __shared__ int smv[1024];
    int i = blockIdx.x * 1024 + threadIdx.x;
    int v = (i < Nn) ? g_cnt[i] : 0;
    smv[threadIdx.x] = v;
    __syncthreads();
    for (int off = 1; off < 1024; off <<= 1) {
        int t = 0;
        if (threadIdx.x >= off) t = smv[threadIdx.x - off];
        __syncthreads();
        if (threadIdx.x >= off) smv[threadIdx.x] += t;
        __syncthreads();
    }
    if (i < Nn) g_off[i] = smv[threadIdx.x];
    if (threadIdx.x == 1023) g_bsum[blockIdx.x] = smv[1023];
}
__global__ void k_scan2() {
    int acc = 0;
    for (int b = 0; b < NB_SCAN; b++) { int t = g_bsum[b]; g_bsum[b] = acc; acc += t; }
}
__global__ void k_scan3() {
    int i = blockIdx.x * 1024 + threadIdx.x;
    if (i < Nn) {
        int incl = g_off[i] + g_bsum[i >> 10];
        int excl = incl - g_cnt[i];
        g_off[i] = excl;
        g_cur[i] = excl;
        g_dinv[i] = rsqrtf((float)g_cnt[i] + 1.0f);
    }
}
__global__ void k_fill(const int* __restrict__ src, const int* __restrict__ dst) {
    int e = blockIdx.x * blockDim.x + threadIdx.x;
    if (e < Ee) {
        int s = src[e], d = dst[e];
        int pos = atomicAdd(&g_cur[d], 1);
        g_csr[pos] = make_int2(s, __float_as_int(g_dinv[s]));
    }
}

// ================= h0 = relu(x @ W_in^T + b_in) =================
__global__ void k_in_linear(const float* __restrict__ x, const float* __restrict__ W,
                            const float* __restrict__ b) {
    extern __shared__ float sm[];
    float* Ws = sm;                 // [64][260]
    float* bb = Ws + 64 * 260;
    float* xb = bb + 64;
    int tid = threadIdx.x;
    for (int i = tid; i < 64 * 64; i += 256) {
        int j = i >> 6, q = i & 63;
        ((float4*)(Ws + j * 260))[q] = ((const float4*)(W + j * 256))[q];
    }
    if (tid < 64) bb[tid] = b[tid];
    __syncthreads();
    int warp = tid >> 5, l = tid & 31;
    float* xw = xb + warp * 1024;
    const float* w0p = Ws + l * 260;
    const float* w1p = Ws + (l + 32) * 260;
    for (int grp = blockIdx.x * 8 + warp; grp < 25000; grp += gridDim.x * 8) {
        int row0 = grp * 4;
        const float4* xg = (const float4*)(x + (size_t)row0 * 256);
        #pragma unroll
        for (int r = 0; r < 4; r++) {
            ((float4*)xw)[r * 64 + l]      = xg[r * 64 + l];
            ((float4*)xw)[r * 64 + l + 32] = xg[r * 64 + l + 32];
        }
        __syncwarp();
        float acc0[4], acc1[4];
        #pragma unroll
        for (int r = 0; r < 4; r++) { acc0[r] = bb[l]; acc1[r] = bb[l + 32]; }
        #pragma unroll 4
        for (int k4 = 0; k4 < 64; k4++) {
            float4 wa = ((const float4*)w0p)[k4];
            float4 wb = ((const float4*)w1p)[k4];
            #pragma unroll
            for (int r = 0; r < 4; r++) {
                float4 xv = ((const float4*)(xw + r * 256))[k4];
                acc0[r] = fmaf(xv.x, wa.x, acc0[r]);
                acc0[r] = fmaf(xv.y, wa.y, acc0[r]);
                acc0[r] = fmaf(xv.z, wa.z, acc0[r]);
                acc0[r] = fmaf(xv.w, wa.w, acc0[r]);
                acc1[r] = fmaf(xv.x, wb.x, acc1[r]);
                acc1[r] = fmaf(xv.y, wb.y, acc1[r]);
                acc1[r] = fmaf(xv.z, wb.z, acc1[r]);
                acc1[r] = fmaf(xv.w, wb.w, acc1[r]);
            }
        }
        #pragma unroll
        for (int r = 0; r < 4; r++) {
            float a0 = fmaxf(acc0[r], 0.f), a1 = fmaxf(acc1[r], 0.f);
            size_t row = row0 + r;
            g_hb[0][row * 64 + l]      = a0;
            g_hb[0][row * 64 + l + 32] = a1;
            g_seq[row * 256 + l]       = a0;
            g_seq[row * 256 + l + 32]  = a1;
        }
        __syncwarp();
    }
}

// ================= fused gather-propagate + token linear =================
// TWO nodes per warp: half h = l>>4 owns node pair*2+h, 16 lanes x float4.
__global__ void k_prop(int inb, int outb, const float* __restrict__ W,
                       const float* __restrict__ b, int slot) {
    __shared__ float Wt[4096];          // Wt[k*64+j] = W[j*64+k]
    __shared__ float bb[64];
    __shared__ float pbuf[8][2][64];
    __shared__ int2  ebuf[8][32];
    int tid = threadIdx.x;
    for (int i = tid; i < 4096; i += 256) {
        int k = i >> 6, j = i & 63;
        Wt[i] = W[j * 64 + k];
    }
    if (tid < 64) bb[tid] = b[tid];
    __syncthreads();
    int warp = tid >> 5, l = tid & 31;
    int half = l >> 4, q = l & 15;
    int2* eb = ebuf[warp];
    const float* hin = g_hb[inb];
    float* hout = g_hb[outb];
    for (int pair = blockIdx.x * 8 + warp; pair < 50000; pair += gridDim.x * 8) {
        int n = pair * 2 + half;
        int beg = g_off[n], cnt = g_cnt[n];
        float dn = g_dinv[n];
        float4 acc = ((const float4*)(hin + (size_t)n * 64))[q];
        acc.x *= dn; acc.y *= dn; acc.z *= dn; acc.w *= dn;
        int cntO = __shfl_xor_sync(0xffffffffu, cnt, 16);
        int cmax = cnt > cntO ? cnt : cntO;
        for (int chunk = 0; chunk < cmax; chunk += 16) {
            if (chunk + q < cnt) eb[l] = __ldg(&g_csr[beg + chunk + q]);
            __syncwarp();
            int m = min(16, cnt - chunk);   // may be <= 0 for this half
            int base = half * 16;
            int i = 0;
            for (; i + 8 <= m; i += 8) {
                float4 v[8]; float w[8];
                #pragma unroll
                for (int u = 0; u < 8; u++) {
                    int2 e = eb[base + i + u];
                    v[u] = __ldg((const float4*)(hin + (size_t)e.x * 64) + q);
                    w[u] = __int_as_float(e.y);
                }
                #pragma unroll
                for (int u = 0; u < 8; u++) {
                    acc.x = fmaf(w[u], v[u].x, acc.x);
                    acc.y = fmaf(w[u], v[u].y, acc.y);
                    acc.z = fmaf(w[u], v[u].z, acc.z);
                    acc.w = fmaf(w[u], v[u].w, acc.w);
                }
            }
            for (; i + 4 <= m; i += 4) {
                float4 v[4]; float w[4];
                #pragma unroll
                for (int u = 0; u < 4; u++) {
                    int2 e = eb[base + i + u];
                    v[u] = __ldg((const float4*)(hin + (size_t)e.x * 64) + q);
                    w[u] = __int_as_float(e.y);
                }
                #pragma unroll
                for (int u = 0; u < 4; u++) {
                    acc.x = fmaf(w[u], v[u].x, acc.x);
                    acc.y = fmaf(w[u], v[u].y, acc.y);
                    acc.z = fmaf(w[u], v[u].z, acc.z);
                    acc.w = fmaf(w[u], v[u].w, acc.w);
                }
            }
            for (; i < m; i++) {
                int2 e = eb[base + i];
                float4 v0 = __ldg((const float4*)(hin + (size_t)e.x * 64) + q);
                float w0 = __int_as_float(e.y);
                acc.x = fmaf(w0, v0.x, acc.x);
                acc.y = fmaf(w0, v0.y, acc.y);
                acc.z = fmaf(w0, v0.z, acc.z);
                acc.w = fmaf(w0, v0.w, acc.w);
            }
            __syncwarp();
        }
        acc.x *= dn; acc.y *= dn; acc.z *= dn; acc.w *= dn;
        ((float4*)(hout + (size_t)n * 64))[q] = acc;
        ((float4*)pbuf[warp][half])[q] = acc;
        __syncwarp();
        // token GEMV: 16 lanes per node, lane computes outputs 4q..4q+3
        const float* pw = pbuf[warp][half];
        float4 tac = *(const float4*)(bb + q * 4);
        #pragma unroll 4
        for (int k4 = 0; k4 < 16; k4++) {
            float4 xv = ((const float4*)pw)[k4];
            #pragma unroll
            for (int kk = 0; kk < 4; kk++) {
                float4 w = *(const float4*)(Wt + (k4 * 4 + kk) * 64 + q * 4);
                float xk = kk == 0 ? xv.x : kk == 1 ? xv.y : kk == 2 ? xv.z : xv.w;
                tac.x = fmaf(xk, w.x, tac.x);
                tac.y = fmaf(xk, w.y, tac.y);
                tac.z = fmaf(xk, w.z, tac.z);
                tac.w = fmaf(xk, w.w, tac.w);
            }
        }
        tac.x = fmaxf(tac.x, 0.f); tac.y = fmaxf(tac.y, 0.f);
        tac.z = fmaxf(tac.z, 0.f); tac.w = fmaxf(tac.w, 0.f);
        *(float4*)(g_seq + (size_t)n * 256 + slot * 64 + q * 4) = tac;
        __syncwarp();
    }
}

// ================= precompute folded attention matrices =================
__global__ void k_pre(const float* __restrict__ inW, const float* __restrict__ inb,
                      const float* __restrict__ WoutG, const float* __restrict__ boutG) {
    int e = blockIdx.x * blockDim.x + threadIdx.x;
    if (e < 4096) {
        int bcol = e >> 6, a = e & 63;
        float m = 0.f, wv = 0.f;
        for (int j = 0; j < 64; j++) {
            m  = fmaf(__ldg(inW + j * 64 + a),   __ldg(inW + (64 + j) * 64 + bcol), m);
            wv = fmaf(__ldg(WoutG + a * 64 + j), __ldg(inW + (128 + j) * 64 + bcol), wv);
        }
        g_Mt[e] = m;
        g_Wvo[e] = wv;
    }
    if (e < 64) {
        float p = 0.f;
        for (int j = 0; j < 64; j++) p = fmaf(__ldg(inb + j), __ldg(inW + (64 + j) * 64 + e), p);
        g_p2[e] = p;
    } else if (e < 128) {
        int a = e - 64;
        float bv = __ldg(boutG + a);
        for (int j = 0; j < 64; j++) bv = fmaf(__ldg(WoutG + a * 64 + j), __ldg(inb + 128 + j), bv);
        g_bvo[a] = bv;
    }
}

// ================= fused transformer + mean + classifier (20 warps) =================
#define SSTR 68
#define FSTR 136
#define WSCR 1168
#define FW   20     // warps per CTA
#define FT   640    // threads per CTA

__global__ void __launch_bounds__(FT, 1) k_former(
    const float* __restrict__ W1_g,   const float* __restrict__ b1_g,
    const float* __restrict__ W2_g,   const float* __restrict__ b2_g,
    const float* __restrict__ ln1w_g, const float* __restrict__ ln1b_g,
    const float* __restrict__ ln2w_g, const float* __restrict__ ln2b_g,
    const float* __restrict__ Wcls_g, const float* __restrict__ bcls_g,
    float* __restrict__ out)
{
    extern __shared__ float sm[];
    float* MtS   = sm;
    float* WvoS  = MtS + 4096;
    float* W1S   = WvoS + 4096;
    float* W2S   = W1S + 8192;
    float* WclsS = W2S + 8192;
    float* p2S   = WclsS + 2560;
    float* bvoS  = p2S + 64;
    float* b1S   = bvoS + 64;
    float* b2S   = b1S + 128;
    float* bclsS = b2S + 64;
    float* ln1wS = bclsS + 40;
    float* ln1bS = ln1wS + 64;
    float* ln2wS = ln1bS + 64;
    float* ln2bS = ln2wS + 64;
    float* scratch = ln2bS + 64;

    int tid = threadIdx.x;
    for (int i = tid; i < 4096; i += FT) { MtS[i] = g_Mt[i]; WvoS[i] = g_Wvo[i]; }
    for (int i = tid; i < 8192; i += FT) { int j = i & 127, k = i >> 7; W1S[k * 128 + j] = W1_g[j * 64 + k]; }
    for (int i = tid; i < 8192; i += FT) { int j = i & 63,  k = i >> 6; W2S[k * 64 + j]  = W2_g[j * 128 + k]; }
    for (int i = tid; i < 2560; i += FT) { int j = i % 40,  k = i / 40; WclsS[k * 40 + j] = Wcls_g[j * 64 + k]; }
    if (tid < 64) {
        p2S[tid] = g_p2[tid]; bvoS[tid] = g_bvo[tid]; b2S[tid] = b2_g[tid];
        ln1wS[tid] = ln1w_g[tid]; ln1bS[tid] = ln1b_g[tid];
        ln2wS[tid] = ln2w_g[tid]; ln2bS[tid] = ln2b_g[tid];
    }
    if (tid >= 64 && tid < 192) b1S[tid - 64] = b1_g[tid - 64];
    if (tid >= 192 && tid < 232) bclsS[tid - 192] = bcls_g[tid - 192];
    __syncthreads();

    int warp = tid >> 5, l = tid & 31;
    float* s   = scratch + warp * WSCR;
    float* z   = s + 272;
    float* b2f = z + 272;
    float* sc  = b2f + 544;
    float* hb  = sc + 16;
    const int t = l >> 3, g = l & 7;
    float* srow = s + t * SSTR;
    const int c1 = 4 * g, c2 = 32 + 4 * g;

    for (int n = blockIdx.x * FW + warp; n < Nn; n += gridDim.x * FW) {
        {
            const float4* sp = (const float4*)(g_seq + (size_t)n * 256);
            int t0 = l >> 4, m = l & 15;
            float4 v0 = sp[l], v1 = sp[l + 32];
            ((float4*)(s + t0 * SSTR))[m] = v0;
            ((float4*)(s + (t0 + 2) * SSTR))[m] = v1;
        }
        __syncwarp();

        // ---- z_t = M s_t (f32x2) ----
        {
            ull p0 = 0, p1 = 0, p2 = 0, p3 = 0;
            #pragma unroll 4
            for (int k4 = 0; k4 < 16; k4++) {
                float4 xv = ((const float4*)srow)[k4];
                #pragma unroll
                for (int kk = 0; kk < 4; kk++) {
                    const float* wrow = MtS + (k4 * 4 + kk) * 64;
                    ulonglong2 wa = *(const ulonglong2*)(wrow + c1);
                    ulonglong2 wb = *(const ulonglong2*)(wrow + c2);
                    float xk = kk == 0 ? xv.x : kk == 1 ? xv.y : kk == 2 ? xv.z : xv.w;
                    ull x2 = bcast2(xk);
                    ffma2(p0, x2, wa.x); ffma2(p1, x2, wa.y);
                    ffma2(p2, x2, wb.x); ffma2(p3, x2, wb.y);
                }
            }
            *(ulonglong2*)(z + t * SSTR + c1) = make_ulonglong2(p0, p1);
            *(ulonglong2*)(z + t * SSTR + c2) = make_ulonglong2(p2, p3);
        }
        __syncwarp();

        // ---- scores + softmax ----
        if (l < 16) {
            int ss = l >> 2, tt = l & 3;
            const float4* ap = (const float4*)(s + ss * SSTR);
            const float4* zp = (const float4*)(z + tt * SSTR);
            const float4* bp = (const float4*)(s + tt * SSTR);
            const float4* pp = (const float4*)p2S;
            float d = 0.f;
            #pragma unroll 4
            for (int k4 = 0; k4 < 16; k4++) {
                float4 a = ap[k4], zz = zp[k4], bq = bp[k4], p = pp[k4];
                d += a.x * zz.x + a.y * zz.y + a.z * zz.z + a.w * zz.w;
                d += p.x * bq.x + p.y * bq.y + p.z * bq.z + p.w * bq.w;
            }
            sc[l] = d * 0.125f;
        }
        __syncwarp();
        if (l < 4) {
            float s0 = sc[l*4], s1 = sc[l*4+1], s2 = sc[l*4+2], s3 = sc[l*4+3];
            float m = fmaxf(fmaxf(s0, s1), fmaxf(s2, s3));
            float e0 = __expf(s0 - m), e1 = __expf(s1 - m), e2 = __expf(s2 - m), e3 = __expf(s3 - m);
            float inv = 1.f / (e0 + e1 + e2 + e3);
            sc[l*4] = e0*inv; sc[l*4+1] = e1*inv; sc[l*4+2] = e2*inv; sc[l*4+3] = e3*inv;
        }
        __syncwarp();

        // ---- m_t = sum_c P[t,c] s_c ----
        {
            float w0 = sc[t*4], w1 = sc[t*4+1], w2 = sc[t*4+2], w3 = sc[t*4+3];
            #pragma unroll
            for (int h = 0; h < 2; h++) {
                int c = h == 0 ? c1 : c2;
                float4 s0 = *(const float4*)(s + c);
                float4 s1 = *(const float4*)(s + SSTR + c);
                float4 s2 = *(const float4*)(s + 2 * SSTR + c);
                float4 s3 = *(const float4*)(s + 3 * SSTR + c);
                float4 r;
                r.x = w0*s0.x + w1*s1.x + w2*s2.x + w3*s3.x;
                r.y = w0*s0.y + w1*s1.y + w2*s2.y + w3*s3.y;
                r.z = w0*s0.z + w1*s1.z + w2*s2.z + w3*s3.z;
                r.w = w0*s0.w + w1*s1.w + w2*s2.w + w3*s3.w;
                *(float4*)(b2f + t * FSTR + c) = r;
            }
        }
        __syncwarp();

        // ---- out = Wvo m + bvo, residual, LN1 (f32x2) ----
        {
            ulonglong2 bv1 = *(const ulonglong2*)(bvoS + c1);
            ulonglong2 bv2 = *(const ulonglong2*)(bvoS + c2);
            ull p0 = bv1.x, p1 = bv1.y, p2 = bv2.x, p3 = bv2.y;
            const float* arow = b2f + t * FSTR;
            #pragma unroll 4
            for (int k4 = 0; k4 < 16; k4++) {
                float4 av = ((const float4*)arow)[k4];
                #pragma unroll
                for (int kk = 0; kk < 4; kk++) {
                    const float* wrow = WvoS + (k4 * 4 + kk) * 64;
                    ulonglong2 wa = *(const ulonglong2*)(wrow + c1);
                    ulonglong2 wb = *(const ulonglong2*)(wrow + c2);
                    float ak = kk == 0 ? av.x : kk == 1 ? av.y : kk == 2 ? av.z : av.w;
                    ull a2 = bcast2(ak);
                    ffma2(p0, a2, wa.x); ffma2(p1, a2, wa.y);
                    ffma2(p2, a2, wb.x); ffma2(p3, a2, wb.y);
                }
            }
            float2 q0 = unpk(p0), q1 = unpk(p1), q2 = unpk(p2), q3 = unpk(p3);
            float4 rs0 = *(const float4*)(srow + c1);
            float4 rs1 = *(const float4*)(srow + c2);
            float r[8];
            r[0] = q0.x + rs0.x; r[1] = q0.y + rs0.y; r[2] = q1.x + rs0.z; r[3] = q1.y + rs0.w;
            r[4] = q2.x + rs1.x; r[5] = q2.y + rs1.y; r[6] = q3.x + rs1.z; r[7] = q3.y + rs1.w;
            float sum = r[0]+r[1]+r[2]+r[3]+r[4]+r[5]+r[6]+r[7];
            sum += __shfl_xor_sync(0xffffffffu, sum, 1);
            sum += __shfl_xor_sync(0xffffffffu, sum, 2);
            sum += __shfl_xor_sync(0xffffffffu, sum, 4);
            float mean = sum * 0.015625f;
            float sq = 0.f;
            #pragma unroll
            for (int i = 0; i < 8; i++) { float dd = r[i] - mean; sq = fmaf(dd, dd, sq); }
            sq += __shfl_xor_sync(0xffffffffu, sq, 1);
            sq += __shfl_xor_sync(0xffffffffu, sq, 2);
            sq += __shfl_xor_sync(0xffffffffu, sq, 4);
            float inv = rsqrtf(sq * 0.015625f + 1e-5f);
            float4 wA = *(const float4*)(ln1wS + c1), wB = *(const float4*)(ln1wS + c2);
            float4 bA = *(const float4*)(ln1bS + c1), bB = *(const float4*)(ln1bS + c2);
            float4 o0, o1;
            o0.x = (r[0]-mean)*inv*wA.x + bA.x; o0.y = (r[1]-mean)*inv*wA.y + bA.y;
            o0.z = (r[2]-mean)*inv*wA.z + bA.z; o0.w = (r[3]-mean)*inv*wA.w + bA.w;
            o1.x = (r[4]-mean)*inv*wB.x + bB.x; o1.y = (r[5]-mean)*inv*wB.y + bB.y;
            o1.z = (r[6]-mean)*inv*wB.z + bB.z; o1.w = (r[7]-mean)*inv*wB.w + bB.w;
            *(float4*)(srow + c1) = o0;
            *(float4*)(srow + c2) = o1;
        }
        __syncwarp();

        // ---- FF1 + exact gelu (f32x2) ----
        {
            ull q[8];
            #pragma unroll
            for (int i = 0; i < 4; i++) {
                ulonglong2 bi = *(const ulonglong2*)(b1S + 32 * i + c1);
                q[2*i] = bi.x; q[2*i+1] = bi.y;
            }
            #pragma unroll 2
            for (int k4 = 0; k4 < 16; k4++) {
                float4 xv = ((const float4*)srow)[k4];
                #pragma unroll
                for (int kk = 0; kk < 4; kk++) {
                    const float* wrow = W1S + (k4 * 4 + kk) * 128;
                    float xk = kk == 0 ? xv.x : kk == 1 ? xv.y : kk == 2 ? xv.z : xv.w;
                    ull x2 = bcast2(xk);
                    #pragma unroll
                    for (int i = 0; i < 4; i++) {
                        ulonglong2 w = *(const ulonglong2*)(wrow + 32 * i + c1);
                        ffma2(q[2*i], x2, w.x);
                        ffma2(q[2*i+1], x2, w.y);
                    }
                }
            }
            float* gp = b2f + t * FSTR;
            #pragma unroll
            for (int i = 0; i < 4; i++) {
                float2 u0 = unpk(q[2*i]), u1 = unpk(q[2*i+1]);
                float4 v;
                v.x = 0.5f * u0.x * (1.0f + erff(u0.x * 0.70710678118f));
                v.y = 0.5f * u0.y * (1.0f + erff(u0.y * 0.70710678118f));
                v.z = 0.5f * u1.x * (1.0f + erff(u1.x * 0.70710678118f));
                v.w = 0.5f * u1.y * (1.0f + erff(u1.y * 0.70710678118f));
                *(float4*)(gp + 32 * i + c1) = v;
            }
        }
        __syncwarp();

        // ---- FF2 + residual + LN2 + token mean (f32x2) ----
        {
            ulonglong2 bv1 = *(const ulonglong2*)(b2S + c1);
            ulonglong2 bv2 = *(const ulonglong2*)(b2S + c2);
            ull p0 = bv1.x, p1 = bv1.y, p2 = bv2.x, p3 = bv2.y;
            const float* grow = b2f + t * FSTR;
            #pragma unroll 2
            for (int k4 = 0; k4 < 32; k4++) {
                float4 gv = ((const float4*)grow)[k4];
                #pragma unroll
                for (int kk = 0; kk < 4; kk++) {
                    const float* wrow = W2S + (k4 * 4 + kk) * 64;
                    ulonglong2 wa = *(const ulonglong2*)(wrow + c1);
                    ulonglong2 wb = *(const ulonglong2*)(wrow + c2);
                    float gk = kk == 0 ? gv.x : kk == 1 ? gv.y : kk == 2 ? gv.z : gv.w;
                    ull g2 = bcast2(gk);
                    ffma2(p0, g2, wa.x); ffma2(p1, g2, wa.y);
                    ffma2(p2, g2, wb.x); ffma2(p3, g2, wb.y);
                }
            }
            float2 q0 = unpk(p0), q1 = unpk(p1), q2 = unpk(p2), q3 = unpk(p3);
            float4 rs0 = *(const float4*)(srow + c1);
            float4 rs1 = *(const float4*)(srow + c2);
            float f[8];
            f[0] = q0.x + rs0.x; f[1] = q0.y + rs0.y; f[2] = q1.x + rs0.z; f[3] = q1.y + rs0.w;
            f[4] = q2.x + rs1.x; f[5] = q2.y + rs1.y; f[6] = q3.x + rs1.z; f[7] = q3.y + rs1.w;
            float sum = f[0]+f[1]+f[2]+f[3]+f[4]+f[5]+f[6]+f[7];
            sum += __shfl_xor_sync(0xffffffffu, sum, 1);
            sum += __shfl_xor_sync(0xffffffffu, sum, 2);
            sum += __shfl_xor_sync(0xffffffffu, sum, 4);
            float mean = sum * 0.015625f;
            float sq = 0.f;
            #pragma unroll
            for (int i = 0; i < 8; i++) { float dd = f[i] - mean; sq = fmaf(dd, dd, sq); }
            sq += __shfl_xor_sync(0xffffffffu, sq, 1);
            sq += __shfl_xor_sync(0xffffffffu, sq, 2);
            sq += __shfl_xor_sync(0xffffffffu, sq, 4);
            float inv = rsqrtf(sq * 0.015625f + 1e-5f);
            float x2v[8];
            #pragma unroll
            for (int i = 0; i < 8; i++) {
                int j = (i < 4) ? (c1 + i) : (c2 + i - 4);
                x2v[i] = (f[i] - mean) * inv * ln2wS[j] + ln2bS[j];
            }
            #pragma unroll
            for (int i = 0; i < 8; i++) {
                float v = x2v[i];
                v += __shfl_xor_sync(0xffffffffu, v, 8);
                v += __shfl_xor_sync(0xffffffffu, v, 16);
                x2v[i] = v * 0.25f;
            }
            if (t == 0) {
                *(float4*)(hb + c1) = make_float4(x2v[0], x2v[1], x2v[2], x2v[3]);
                *(float4*)(hb + c2) = make_float4(x2v[4], x2v[5], x2v[6], x2v[7]);
            }
        }
        __syncwarp();

        // ---- classifier ----
        {
            float o0 = bclsS[l];
            float o1 = bclsS[32 + g];
            #pragma unroll 4
            for (int k4 = 0; k4 < 16; k4++) {
                float4 hv = ((const float4*)hb)[k4];
                const float* wr = WclsS + k4 * 160;
                o0 = fmaf(hv.x, wr[l], o0);        o1 = fmaf(hv.x, wr[32 + g], o1);
                o0 = fmaf(hv.y, wr[40 + l], o0);   o1 = fmaf(hv.y, wr[72 + g], o1);
                o0 = fmaf(hv.z, wr[80 + l], o0);   o1 = fmaf(hv.z, wr[112 + g], o1);
                o0 = fmaf(hv.w, wr[120 + l], o0);  o1 = fmaf(hv.w, wr[152 + g], o1);
            }
            out[(size_t)n * 40 + l] = o0;
            if (l < 8) out[(size_t)n * 40 + 32 + l] = o1;
        }
        __syncwarp();
    }
}

extern "C" void kernel_launch(void* const* d_in, const int* in_sizes, int n_in,
                              void* d_out, int out_size) {
    const float* x     = (const float*)d_in[0];
    const int*   ei    = (const int*)d_in[1];
    const float* W_in  = (const float*)d_in[2];
    const float* b_in  = (const float*)d_in[3];
    const float* sg_W  = (const float*)d_in[4];
    const float* sg_b  = (const float*)d_in[5];
    const float* inW   = (const float*)d_in[6];
    const float* inb   = (const float*)d_in[7];
    const float* Wout  = (const float*)d_in[8];
    const float* bout  = (const float*)d_in[9];
    const float* W1    = (const float*)d_in[10];
    const float* b1    = (const float*)d_in[11];
    const float* W2    = (const float*)d_in[12];
    const float* b2    = (const float*)d_in[13];
    const float* ln1w  = (const float*)d_in[14];
    const float* ln1b  = (const float*)d_in[15];
    const float* ln2w  = (const float*)d_in[16];
    const float* ln2b  = (const float*)d_in[17];
    const float* Wcls  = (const float*)d_in[18];
    const float* bcls  = (const float*)d_in[19];
    float* out = (float*)d_out;

    // former smem: (27752 + 20*1168) * 4 = 204448 B
    cudaFuncSetAttribute(k_in_linear, cudaFuncAttributeMaxDynamicSharedMemorySize, 99584);
    cudaFuncSetAttribute(k_former,    cudaFuncAttributeMaxDynamicSharedMemorySize, 204448);

    k_init<<<(Nn + 255) / 256, 256>>>();
    k_count<<<(Ee + 255) / 256, 256>>>(ei + Ee);
    k_scan1<<<NB_SCAN, 1024>>>();
    k_scan2<<<1, 1>>>();
    k_scan3<<<NB_SCAN, 1024>>>();
    k_fill<<<(Ee + 255) / 256, 256>>>(ei, ei + Ee);

    k_in_linear<<<592, 256, 99584>>>(x, W_in, b_in);
    k_pre<<<16, 256>>>(inW, inb, Wout, bout);

    const int ib[3] = {0, 1, 2};
    const int ob[3] = {1, 2, 1};
    for (int hop = 0; hop < 3; hop++) {
        k_prop<<<1184, 256>>>(ib[hop], ob[hop], sg_W + hop * 4096, sg_b + hop * 64, hop + 1);
    }

    k_former<<<148, FT, 204448>>>(W1, b1, W2, b2, ln1w, ln1b, ln2w, ln2b, Wcls, bcls, out);
}

// round 9
// speedup vs baseline: 2.2281x; 1.0188x over previous
#include <cuda_runtime.h>
#include <math.h>

#define Nn   100000
#define Ee   1600000
#define NH   (Nn * 64)
#define CHUNK 676   // ceil(100000/148)

typedef unsigned long long ull;
__device__ __forceinline__ ull bcast2(float x) {
    ull r; asm("mov.b64 %0, {%1, %1};" : "=l"(r) : "f"(x)); return r;
}
__device__ __forceinline__ void ffma2(ull& d, ull a, ull b) {
    asm("fma.rn.f32x2 %0, %1, %2, %0;" : "+l"(d) : "l"(a), "l"(b));
}
__device__ __forceinline__ float2 unpk(ull v) {
    float2 f; asm("mov.b64 {%0, %1}, %2;" : "=f"(f.x), "=f"(f.y) : "l"(v)); return f;
}

// ---- persistent device scratch ----
__device__ float g_dinv[Nn];
__device__ int   g_cnt[Nn];
__device__ int   g_off[Nn];
__device__ int   g_cur[Nn];
__device__ int   g_bsum[256];
__device__ int2  g_csr[Ee];
__device__ float g_hb[3][NH];
__device__ float g_seq[(size_t)Nn * 256];
__device__ float g_Mt[4096];
__device__ float g_Wvo[4096];
__device__ float g_p2[64];
__device__ float g_bvo[64];

// ---- grid-wide barrier (all CTAs resident: grid=148) ----
__device__ unsigned g_barcnt = 0;
__device__ volatile unsigned g_barsense = 0;

__device__ __forceinline__ void gridbar(unsigned& sense) {
    __syncthreads();
    if (threadIdx.x == 0) {
        sense ^= 1u;
        __threadfence();
        unsigned old = atomicAdd(&g_barcnt, 1u);
        if (old == gridDim.x - 1) {
            atomicExch(&g_barcnt, 0u);
            __threadfence();
            g_barsense = sense;
        } else {
            while (g_barsense != sense) { }
        }
    }
    __syncthreads();
}

// ================= single-kernel CSR build + dinv =================
__global__ void __launch_bounds__(256) k_build(const int* __restrict__ src,
                                               const int* __restrict__ dst) {
    __shared__ int part[256];
    int tid = threadIdx.x, cta = blockIdx.x;
    int gs = gridDim.x * 256;
    unsigned sense = g_barsense;

    // phase 1: zero counts
    for (int i = cta * 256 + tid; i < Nn; i += gs) g_cnt[i] = 0;
    gridbar(sense);
    // phase 2: count degrees
    for (int e = cta * 256 + tid; e < Ee; e += gs) atomicAdd(&g_cnt[dst[e]], 1);
    gridbar(sense);
    // phase 3: per-CTA partial sums over contiguous chunk
    int base = cta * CHUNK;
    int lim = min(base + CHUNK, Nn);
    int i0 = base + tid * 3;
    int c0 = (i0     < lim) ? g_cnt[i0]     : 0;
    int c1 = (i0 + 1 < lim) ? g_cnt[i0 + 1] : 0;
    int c2 = (i0 + 2 < lim) ? g_cnt[i0 + 2] : 0;
    int tsum = c0 + c1 + c2;
    part[tid] = tsum;
    __syncthreads();
    for (int off = 1; off < 256; off <<= 1) {
        int v = (tid >= off) ? part[tid - off] : 0;
        __syncthreads();
        if (tid >= off) part[tid] += v;
        __syncthreads();
    }
    if (tid == 255) g_bsum[cta] = part[255];
    gridbar(sense);
    // phase 4: CTA0 scans CTA partials
    if (cta == 0 && tid == 0) {
        int acc = 0;
        for (int b = 0; b < (int)gridDim.x; b++) { int t = g_bsum[b]; g_bsum[b] = acc; acc += t; }
    }
    gridbar(sense);
    // phase 5: write offsets / cursors / dinv
    {
        int ctaoff = g_bsum[cta];
        int texcl = ctaoff + part[tid] - tsum;
        if (i0 < lim) {
            g_off[i0] = texcl; g_cur[i0] = texcl;
            g_dinv[i0] = rsqrtf((float)c0 + 1.0f);
        }
        if (i0 + 1 < lim) {
            int ex = texcl + c0;
            g_off[i0 + 1] = ex; g_cur[i0 + 1] = ex;
            g_dinv[i0 + 1] = rsqrtf((float)c1 + 1.0f);
        }
        if (i0 + 2 < lim) {
            int ex = texcl + c0 + c1;
            g_off[i0 + 2] = ex; g_cur[i0 + 2] = ex;
            g_dinv[i0 + 2] = rsqrtf((float)c2 + 1.0f);
        }
    }
    gridbar(sense);
    // phase 6: fill CSR
    for (int e = cta * 256 + tid; e < Ee; e += gs) {
        int s = src[e], d = dst[e];
        int pos = atomicAdd(&g_cur[d], 1);
        g_csr[pos] = make_int2(s, __float_as_int(g_dinv[s]));
    }
}

// ================= h0 = relu(x @ W_in^T + b_in) =================
__global__ void k_in_linear(const float* __restrict__ x, const float* __restrict__ W,
                            const float* __restrict__ b) {
    extern __shared__ float sm[];
    float* Ws = sm;                 // [64][260]
    float* bb = Ws + 64 * 260;
    float* xb = bb + 64;
    int tid = threadIdx.x;
    for (int i = tid; i < 64 * 64; i += 256) {
        int j = i >> 6, q = i & 63;
        ((float4*)(Ws + j * 260))[q] = ((const float4*)(W + j * 256))[q];
    }
    if (tid < 64) bb[tid] = b[tid];
    __syncthreads();
    int warp = tid >> 5, l = tid & 31;
    float* xw = xb + warp * 1024;
    const float* w0p = Ws + l * 260;
    const float* w1p = Ws + (l + 32) * 260;
    for (int grp = blockIdx.x * 8 + warp; grp < 25000; grp += gridDim.x * 8) {
        int row0 = grp * 4;
        const float4* xg = (const float4*)(x + (size_t)row0 * 256);
        #pragma unroll
        for (int r = 0; r < 4; r++) {
            ((float4*)xw)[r * 64 + l]      = xg[r * 64 + l];
            ((float4*)xw)[r * 64 + l + 32] = xg[r * 64 + l + 32];
        }
        __syncwarp();
        float acc0[4], acc1[4];
        #pragma unroll
        for (int r = 0; r < 4; r++) { acc0[r] = bb[l]; acc1[r] = bb[l + 32]; }
        #pragma unroll 4
        for (int k4 = 0; k4 < 64; k4++) {
            float4 wa = ((const float4*)w0p)[k4];
            float4 wb = ((const float4*)w1p)[k4];
            #pragma unroll
            for (int r = 0; r < 4; r++) {
                float4 xv = ((const float4*)(xw + r * 256))[k4];
                acc0[r] = fmaf(xv.x, wa.x, acc0[r]);
                acc0[r] = fmaf(xv.y, wa.y, acc0[r]);
                acc0[r] = fmaf(xv.z, wa.z, acc0[r]);
                acc0[r] = fmaf(xv.w, wa.w, acc0[r]);
                acc1[r] = fmaf(xv.x, wb.x, acc1[r]);
                acc1[r] = fmaf(xv.y, wb.y, acc1[r]);
                acc1[r] = fmaf(xv.z, wb.z, acc1[r]);
                acc1[r] = fmaf(xv.w, wb.w, acc1[r]);
            }
        }
        #pragma unroll
        for (int r = 0; r < 4; r++) {
            float a0 = fmaxf(acc0[r], 0.f), a1 = fmaxf(acc1[r], 0.f);
            size_t row = row0 + r;
            g_hb[0][row * 64 + l]      = a0;
            g_hb[0][row * 64 + l + 32] = a1;
            g_seq[row * 256 + l]       = a0;
            g_seq[row * 256 + l + 32]  = a1;
        }
        __syncwarp();
    }
}

// ================= precompute folded attention matrices =================
__global__ void k_pre(const float* __restrict__ inW, const float* __restrict__ inb,
                      const float* __restrict__ WoutG, const float* __restrict__ boutG) {
    int e = blockIdx.x * blockDim.x + threadIdx.x;
    if (e < 4096) {
        int bcol = e >> 6, a = e & 63;
        float m = 0.f, wv = 0.f;
        for (int j = 0; j < 64; j++) {
            m  = fmaf(__ldg(inW + j * 64 + a),   __ldg(inW + (64 + j) * 64 + bcol), m);
            wv = fmaf(__ldg(WoutG + a * 64 + j), __ldg(inW + (128 + j) * 64 + bcol), wv);
        }
        g_Mt[e] = m;
        g_Wvo[e] = wv;
    }
    if (e < 64) {
        float p = 0.f;
        for (int j = 0; j < 64; j++) p = fmaf(__ldg(inb + j), __ldg(inW + (64 + j) * 64 + e), p);
        g_p2[e] = p;
    } else if (e < 128) {
        int a = e - 64;
        float bv = __ldg(boutG + a);
        for (int j = 0; j < 64; j++) bv = fmaf(__ldg(WoutG + a * 64 + j), __ldg(inb + 128 + j), bv);
        g_bvo[a] = bv;
    }
}

// ================= fused gather-propagate + token linear =================
// TWO nodes per warp, 16 lanes x float4 each. Register-capped for 4 CTAs/SM.
__global__ void __launch_bounds__(256, 4) k_prop(int inb, int outb,
                                                 const float* __restrict__ W,
                                                 const float* __restrict__ b, int slot) {
    __shared__ float Wt[4096];          // Wt[k*64+j] = W[j*64+k]
    __shared__ float bb[64];
    __shared__ float pbuf[8][2][64];
    __shared__ int2  ebuf[8][32];
    int tid = threadIdx.x;
    for (int i = tid; i < 4096; i += 256) {
        int k = i >> 6, j = i & 63;
        Wt[i] = W[j * 64 + k];
    }
    if (tid < 64) bb[tid] = b[tid];
    __syncthreads();
    int warp = tid >> 5, l = tid & 31;
    int half = l >> 4, q = l & 15;
    int2* eb = ebuf[warp];
    const float* hin = g_hb[inb];
    float* hout = g_hb[outb];
    for (int pair = blockIdx.x * 8 + warp; pair < 50000; pair += gridDim.x * 8) {
        int n = pair * 2 + half;
        int beg = g_off[n], cnt = g_cnt[n];
        float dn = g_dinv[n];
        float4 acc = ((const float4*)(hin + (size_t)n * 64))[q];
        acc.x *= dn; acc.y *= dn; acc.z *= dn; acc.w *= dn;
        int cntO = __shfl_xor_sync(0xffffffffu, cnt, 16);
        int cmax = cnt > cntO ? cnt : cntO;
        for (int chunk = 0; chunk < cmax; chunk += 16) {
            if (chunk + q < cnt) eb[l] = __ldg(&g_csr[beg + chunk + q]);
            __syncwarp();
            int m = min(16, cnt - chunk);
            int base = half * 16;
            int i = 0;
            for (; i + 4 <= m; i += 4) {
                float4 v[4]; float w[4];
                #pragma unroll
                for (int u = 0; u < 4; u++) {
                    int2 e = eb[base + i + u];
                    v[u] = __ldg((const float4*)(hin + (size_t)e.x * 64) + q);
                    w[u] = __int_as_float(e.y);
                }
                #pragma unroll
                for (int u = 0; u < 4; u++) {
                    acc.x = fmaf(w[u], v[u].x, acc.x);
                    acc.y = fmaf(w[u], v[u].y, acc.y);
                    acc.z = fmaf(w[u], v[u].z, acc.z);
                    acc.w = fmaf(w[u], v[u].w, acc.w);
                }
            }
            for (; i < m; i++) {
                int2 e = eb[base + i];
                float4 v0 = __ldg((const float4*)(hin + (size_t)e.x * 64) + q);
                float w0 = __int_as_float(e.y);
                acc.x = fmaf(w0, v0.x, acc.x);
                acc.y = fmaf(w0, v0.y, acc.y);
                acc.z = fmaf(w0, v0.z, acc.z);
                acc.w = fmaf(w0, v0.w, acc.w);
            }
            __syncwarp();
        }
        acc.x *= dn; acc.y *= dn; acc.z *= dn; acc.w *= dn;
        ((float4*)(hout + (size_t)n * 64))[q] = acc;
        ((float4*)pbuf[warp][half])[q] = acc;
        __syncwarp();
        // token GEMV: 16 lanes per node, lane computes outputs 4q..4q+3
        const float* pw = pbuf[warp][half];
        float4 tac = *(const float4*)(bb + q * 4);
        #pragma unroll 4
        for (int k4 = 0; k4 < 16; k4++) {
            float4 xv = ((const float4*)pw)[k4];
            #pragma unroll
            for (int kk = 0; kk < 4; kk++) {
                float4 w = *(const float4*)(Wt + (k4 * 4 + kk) * 64 + q * 4);
                float xk = kk == 0 ? xv.x : kk == 1 ? xv.y : kk == 2 ? xv.z : xv.w;
                tac.x = fmaf(xk, w.x, tac.x);
                tac.y = fmaf(xk, w.y, tac.y);
                tac.z = fmaf(xk, w.z, tac.z);
                tac.w = fmaf(xk, w.w, tac.w);
            }
        }
        tac.x = fmaxf(tac.x, 0.f); tac.y = fmaxf(tac.y, 0.f);
        tac.z = fmaxf(tac.z, 0.f); tac.w = fmaxf(tac.w, 0.f);
        *(float4*)(g_seq + (size_t)n * 256 + slot * 64 + q * 4) = tac;
        __syncwarp();
    }
}

// ================= fused transformer + mean + classifier (R8 proven) =================
#define SSTR 68
#define FSTR 136
#define WSCR 1168
#define FW   20
#define FT   640

__global__ void __launch_bounds__(FT, 1) k_former(
    const float* __restrict__ W1_g,   const float* __restrict__ b1_g,
    const float* __restrict__ W2_g,   const float* __restrict__ b2_g,
    const float* __restrict__ ln1w_g, const float* __restrict__ ln1b_g,
    const float* __restrict__ ln2w_g, const float* __restrict__ ln2b_g,
    const float* __restrict__ Wcls_g, const float* __restrict__ bcls_g,
    float* __restrict__ out)
{
    extern __shared__ float sm[];
    float* MtS   = sm;
    float* WvoS  = MtS + 4096;
    float* W1S   = WvoS + 4096;
    float* W2S   = W1S + 8192;
    float* WclsS = W2S + 8192;
    float* p2S   = WclsS + 2560;
    float* bvoS  = p2S + 64;
    float* b1S   = bvoS + 64;
    float* b2S   = b1S + 128;
    float* bclsS = b2S + 64;
    float* ln1wS = bclsS + 40;
    float* ln1bS = ln1wS + 64;
    float* ln2wS = ln1bS + 64;
    float* ln2bS = ln2wS + 64;
    float* scratch = ln2bS + 64;

    int tid = threadIdx.x;
    for (int i = tid; i < 4096; i += FT) { MtS[i] = g_Mt[i]; WvoS[i] = g_Wvo[i]; }
    for (int i = tid; i < 8192; i += FT) { int j = i & 127, k = i >> 7; W1S[k * 128 + j] = W1_g[j * 64 + k]; }
    for (int i = tid; i < 8192; i += FT) { int j = i & 63,  k = i >> 6; W2S[k * 64 + j]  = W2_g[j * 128 + k]; }
    for (int i = tid; i < 2560; i += FT) { int j = i % 40,  k = i / 40; WclsS[k * 40 + j] = Wcls_g[j * 64 + k]; }
    if (tid < 64) {
        p2S[tid] = g_p2[tid]; bvoS[tid] = g_bvo[tid]; b2S[tid] = b2_g[tid];
        ln1wS[tid] = ln1w_g[tid]; ln1bS[tid] = ln1b_g[tid];
        ln2wS[tid] = ln2w_g[tid]; ln2bS[tid] = ln2b_g[tid];
    }
    if (tid >= 64 && tid < 192) b1S[tid - 64] = b1_g[tid - 64];
    if (tid >= 192 && tid < 232) bclsS[tid - 192] = bcls_g[tid - 192];
    __syncthreads();

    int warp = tid >> 5, l = tid & 31;
    float* s   = scratch + warp * WSCR;
    float* z   = s + 272;
    float* b2f = z + 272;
    float* sc  = b2f + 544;
    float* hb  = sc + 16;
    const int t = l >> 3, g = l & 7;
    float* srow = s + t * SSTR;
    const int c1 = 4 * g, c2 = 32 + 4 * g;

    for (int n = blockIdx.x * FW + warp; n < Nn; n += gridDim.x * FW) {
        {
            const float4* sp = (const float4*)(g_seq + (size_t)n * 256);
            int t0 = l >> 4, m = l & 15;
            float4 v0 = sp[l], v1 = sp[l + 32];
            ((float4*)(s + t0 * SSTR))[m] = v0;
            ((float4*)(s + (t0 + 2) * SSTR))[m] = v1;
        }
        __syncwarp();

        // ---- z_t = M s_t (f32x2) ----
        {
            ull p0 = 0, p1 = 0, p2 = 0, p3 = 0;
            #pragma unroll 4
            for (int k4 = 0; k4 < 16; k4++) {
                float4 xv = ((const float4*)srow)[k4];
                #pragma unroll
                for (int kk = 0; kk < 4; kk++) {
                    const float* wrow = MtS + (k4 * 4 + kk) * 64;
                    ulonglong2 wa = *(const ulonglong2*)(wrow + c1);
                    ulonglong2 wb = *(const ulonglong2*)(wrow + c2);
                    float xk = kk == 0 ? xv.x : kk == 1 ? xv.y : kk == 2 ? xv.z : xv.w;
                    ull x2 = bcast2(xk);
                    ffma2(p0, x2, wa.x); ffma2(p1, x2, wa.y);
                    ffma2(p2, x2, wb.x); ffma2(p3, x2, wb.y);
                }
            }
            *(ulonglong2*)(z + t * SSTR + c1) = make_ulonglong2(p0, p1);
            *(ulonglong2*)(z + t * SSTR + c2) = make_ulonglong2(p2, p3);
        }
        __syncwarp();

        // ---- scores + softmax ----
        if (l < 16) {
            int ss = l >> 2, tt = l & 3;
            const float4* ap = (const float4*)(s + ss * SSTR);
            const float4* zp = (const float4*)(z + tt * SSTR);
            const float4* bp = (const float4*)(s + tt * SSTR);
            const float4* pp = (const float4*)p2S;
            float d = 0.f;
            #pragma unroll 4
            for (int k4 = 0; k4 < 16; k4++) {
                float4 a = ap[k4], zz = zp[k4], bq = bp[k4], p = pp[k4];
                d += a.x * zz.x + a.y * zz.y + a.z * zz.z + a.w * zz.w;
                d += p.x * bq.x + p.y * bq.y + p.z * bq.z + p.w * bq.w;
            }
            sc[l] = d * 0.125f;
        }
        __syncwarp();
        if (l < 4) {
            float s0 = sc[l*4], s1 = sc[l*4+1], s2 = sc[l*4+2], s3 = sc[l*4+3];
            float m = fmaxf(fmaxf(s0, s1), fmaxf(s2, s3));
            float e0 = __expf(s0 - m), e1 = __expf(s1 - m), e2 = __expf(s2 - m), e3 = __expf(s3 - m);
            float inv = 1.f / (e0 + e1 + e2 + e3);
            sc[l*4] = e0*inv; sc[l*4+1] = e1*inv; sc[l*4+2] = e2*inv; sc[l*4+3] = e3*inv;
        }
        __syncwarp();

        // ---- m_t = sum_c P[t,c] s_c ----
        {
            float w0 = sc[t*4], w1 = sc[t*4+1], w2 = sc[t*4+2], w3 = sc[t*4+3];
            #pragma unroll
            for (int h = 0; h < 2; h++) {
                int c = h == 0 ? c1 : c2;
                float4 s0 = *(const float4*)(s + c);
                float4 s1 = *(const float4*)(s + SSTR + c);
                float4 s2 = *(const float4*)(s + 2 * SSTR + c);
                float4 s3 = *(const float4*)(s + 3 * SSTR + c);
                float4 r;
                r.x = w0*s0.x + w1*s1.x + w2*s2.x + w3*s3.x;
                r.y = w0*s0.y + w1*s1.y + w2*s2.y + w3*s3.y;
                r.z = w0*s0.z + w1*s1.z + w2*s2.z + w3*s3.z;
                r.w = w0*s0.w + w1*s1.w + w2*s2.w + w3*s3.w;
                *(float4*)(b2f + t * FSTR + c) = r;
            }
        }
        __syncwarp();

        // ---- out = Wvo m + bvo, residual, LN1 (f32x2) ----
        {
            ulonglong2 bv1 = *(const ulonglong2*)(bvoS + c1);
            ulonglong2 bv2 = *(const ulonglong2*)(bvoS + c2);
            ull p0 = bv1.x, p1 = bv1.y, p2 = bv2.x, p3 = bv2.y;
            const float* arow = b2f + t * FSTR;
            #pragma unroll 4
            for (int k4 = 0; k4 < 16; k4++) {
                float4 av = ((const float4*)arow)[k4];
                #pragma unroll
                for (int kk = 0; kk < 4; kk++) {
                    const float* wrow = WvoS + (k4 * 4 + kk) * 64;
                    ulonglong2 wa = *(const ulonglong2*)(wrow + c1);
                    ulonglong2 wb = *(const ulonglong2*)(wrow + c2);
                    float ak = kk == 0 ? av.x : kk == 1 ? av.y : kk == 2 ? av.z : av.w;
                    ull a2 = bcast2(ak);
                    ffma2(p0, a2, wa.x); ffma2(p1, a2, wa.y);
                    ffma2(p2, a2, wb.x); ffma2(p3, a2, wb.y);
                }
            }
            float2 q0 = unpk(p0), q1 = unpk(p1), q2 = unpk(p2), q3 = unpk(p3);
            float4 rs0 = *(const float4*)(srow + c1);
            float4 rs1 = *(const float4*)(srow + c2);
            float r[8];
            r[0] = q0.x + rs0.x; r[1] = q0.y + rs0.y; r[2] = q1.x + rs0.z; r[3] = q1.y + rs0.w;
            r[4] = q2.x + rs1.x; r[5] = q2.y + rs1.y; r[6] = q3.x + rs1.z; r[7] = q3.y + rs1.w;
            float sum = r[0]+r[1]+r[2]+r[3]+r[4]+r[5]+r[6]+r[7];
            sum += __shfl_xor_sync(0xffffffffu, sum, 1);
            sum += __shfl_xor_sync(0xffffffffu, sum, 2);
            sum += __shfl_xor_sync(0xffffffffu, sum, 4);
            float mean = sum * 0.015625f;
            float sq = 0.f;
            #pragma unroll
            for (int i = 0; i < 8; i++) { float dd = r[i] - mean; sq = fmaf(dd, dd, sq); }
            sq += __shfl_xor_sync(0xffffffffu, sq, 1);
            sq += __shfl_xor_sync(0xffffffffu, sq, 2);
            sq += __shfl_xor_sync(0xffffffffu, sq, 4);
            float inv = rsqrtf(sq * 0.015625f + 1e-5f);
            float4 wA = *(const float4*)(ln1wS + c1), wB = *(const float4*)(ln1wS + c2);
            float4 bA = *(const float4*)(ln1bS + c1), bB = *(const float4*)(ln1bS + c2);
            float4 o0, o1;
            o0.x = (r[0]-mean)*inv*wA.x + bA.x; o0.y = (r[1]-mean)*inv*wA.y + bA.y;
            o0.z = (r[2]-mean)*inv*wA.z + bA.z; o0.w = (r[3]-mean)*inv*wA.w + bA.w;
            o1.x = (r[4]-mean)*inv*wB.x + bB.x; o1.y = (r[5]-mean)*inv*wB.y + bB.y;
            o1.z = (r[6]-mean)*inv*wB.z + bB.z; o1.w = (r[7]-mean)*inv*wB.w + bB.w;
            *(float4*)(srow + c1) = o0;
            *(float4*)(srow + c2) = o1;
        }
        __syncwarp();

        // ---- FF1 + exact gelu (f32x2) ----
        {
            ull q[8];
            #pragma unroll
            for (int i = 0; i < 4; i++) {
                ulonglong2 bi = *(const ulonglong2*)(b1S + 32 * i + c1);
                q[2*i] = bi.x; q[2*i+1] = bi.y;
            }
            #pragma unroll 2
            for (int k4 = 0; k4 < 16; k4++) {
                float4 xv = ((const float4*)srow)[k4];
                #pragma unroll
                for (int kk = 0; kk < 4; kk++) {
                    const float* wrow = W1S + (k4 * 4 + kk) * 128;
                    float xk = kk == 0 ? xv.x : kk == 1 ? xv.y : kk == 2 ? xv.z : xv.w;
                    ull x2 = bcast2(xk);
                    #pragma unroll
                    for (int i = 0; i < 4; i++) {
                        ulonglong2 w = *(const ulonglong2*)(wrow + 32 * i + c1);
                        ffma2(q[2*i], x2, w.x);
                        ffma2(q[2*i+1], x2, w.y);
                    }
                }
            }
            float* gp = b2f + t * FSTR;
            #pragma unroll
            for (int i = 0; i < 4; i++) {
                float2 u0 = unpk(q[2*i]), u1 = unpk(q[2*i+1]);
                float4 v;
                v.x = 0.5f * u0.x * (1.0f + erff(u0.x * 0.70710678118f));
                v.y = 0.5f * u0.y * (1.0f + erff(u0.y * 0.70710678118f));
                v.z = 0.5f * u1.x * (1.0f + erff(u1.x * 0.70710678118f));
                v.w = 0.5f * u1.y * (1.0f + erff(u1.y * 0.70710678118f));
                *(float4*)(gp + 32 * i + c1) = v;
            }
        }
        __syncwarp();

        // ---- FF2 + residual + LN2 + token mean (f32x2) ----
        {
            ulonglong2 bv1 = *(const ulonglong2*)(b2S + c1);
            ulonglong2 bv2 = *(const ulonglong2*)(b2S + c2);
            ull p0 = bv1.x, p1 = bv1.y, p2 = bv2.x, p3 = bv2.y;
            const float* grow = b2f + t * FSTR;
            #pragma unroll 2
            for (int k4 = 0; k4 < 32; k4++) {
                float4 gv = ((const float4*)grow)[k4];
                #pragma unroll
                for (int kk = 0; kk < 4; kk++) {
                    const float* wrow = W2S + (k4 * 4 + kk) * 64;
                    ulonglong2 wa = *(const ulonglong2*)(wrow + c1);
                    ulonglong2 wb = *(const ulonglong2*)(wrow + c2);
                    float gk = kk == 0 ? gv.x : kk == 1 ? gv.y : kk == 2 ? gv.z : gv.w;
                    ull g2 = bcast2(gk);
                    ffma2(p0, g2, wa.x); ffma2(p1, g2, wa.y);
                    ffma2(p2, g2, wb.x); ffma2(p3, g2, wb.y);
                }
            }
            float2 q0 = unpk(p0), q1 = unpk(p1), q2 = unpk(p2), q3 = unpk(p3);
            float4 rs0 = *(const float4*)(srow + c1);
            float4 rs1 = *(const float4*)(srow + c2);
            float f[8];
            f[0] = q0.x + rs0.x; f[1] = q0.y + rs0.y; f[2] = q1.x + rs0.z; f[3] = q1.y + rs0.w;
            f[4] = q2.x + rs1.x; f[5] = q2.y + rs1.y; f[6] = q3.x + rs1.z; f[7] = q3.y + rs1.w;
            float sum = f[0]+f[1]+f[2]+f[3]+f[4]+f[5]+f[6]+f[7];
            sum += __shfl_xor_sync(0xffffffffu, sum, 1);
            sum += __shfl_xor_sync(0xffffffffu, sum, 2);
            sum += __shfl_xor_sync(0xffffffffu, sum, 4);
            float mean = sum * 0.015625f;
            float sq = 0.f;
            #pragma unroll
            for (int i = 0; i < 8; i++) { float dd = f[i] - mean; sq = fmaf(dd, dd, sq); }
            sq += __shfl_xor_sync(0xffffffffu, sq, 1);
            sq += __shfl_xor_sync(0xffffffffu, sq, 2);
            sq += __shfl_xor_sync(0xffffffffu, sq, 4);
            float inv = rsqrtf(sq * 0.015625f + 1e-5f);
            float x2v[8];
            #pragma unroll
            for (int i = 0; i < 8; i++) {
                int j = (i < 4) ? (c1 + i) : (c2 + i - 4);
                x2v[i] = (f[i] - mean) * inv * ln2wS[j] + ln2bS[j];
            }
            #pragma unroll
            for (int i = 0; i < 8; i++) {
                float v = x2v[i];
                v += __shfl_xor_sync(0xffffffffu, v, 8);
                v += __shfl_xor_sync(0xffffffffu, v, 16);
                x2v[i] = v * 0.25f;
            }
            if (t == 0) {
                *(float4*)(hb + c1) = make_float4(x2v[0], x2v[1], x2v[2], x2v[3]);
                *(float4*)(hb + c2) = make_float4(x2v[4], x2v[5], x2v[6], x2v[7]);
            }
        }
        __syncwarp();

        // ---- classifier ----
        {
            float o0 = bclsS[l];
            float o1 = bclsS[32 + g];
            #pragma unroll 4
            for (int k4 = 0; k4 < 16; k4++) {
                float4 hv = ((const float4*)hb)[k4];
                const float* wr = WclsS + k4 * 160;
                o0 = fmaf(hv.x, wr[l], o0);        o1 = fmaf(hv.x, wr[32 + g], o1);
                o0 = fmaf(hv.y, wr[40 + l], o0);   o1 = fmaf(hv.y, wr[72 + g], o1);
                o0 = fmaf(hv.z, wr[80 + l], o0);   o1 = fmaf(hv.z, wr[112 + g], o1);
                o0 = fmaf(hv.w, wr[120 + l], o0);  o1 = fmaf(hv.w, wr[152 + g], o1);
            }
            out[(size_t)n * 40 + l] = o0;
            if (l < 8) out[(size_t)n * 40 + 32 + l] = o1;
        }
        __syncwarp();
    }
}

extern "C" void kernel_launch(void* const* d_in, const int* in_sizes, int n_in,
                              void* d_out, int out_size) {
    const float* x     = (const float*)d_in[0];
    const int*   ei    = (const int*)d_in[1];
    const float* W_in  = (const float*)d_in[2];
    const float* b_in  = (const float*)d_in[3];
    const float* sg_W  = (const float*)d_in[4];
    const float* sg_b  = (const float*)d_in[5];
    const float* inW   = (const float*)d_in[6];
    const float* inb   = (const float*)d_in[7];
    const float* Wout  = (const float*)d_in[8];
    const float* bout  = (const float*)d_in[9];
    const float* W1    = (const float*)d_in[10];
    const float* b1    = (const float*)d_in[11];
    const float* W2    = (const float*)d_in[12];
    const float* b2    = (const float*)d_in[13];
    const float* ln1w  = (const float*)d_in[14];
    const float* ln1b  = (const float*)d_in[15];
    const float* ln2w  = (const float*)d_in[16];
    const float* ln2b  = (const float*)d_in[17];
    const float* Wcls  = (const float*)d_in[18];
    const float* bcls  = (const float*)d_in[19];
    float* out = (float*)d_out;

    cudaFuncSetAttribute(k_in_linear, cudaFuncAttributeMaxDynamicSharedMemorySize, 99584);
    cudaFuncSetAttribute(k_former,    cudaFuncAttributeMaxDynamicSharedMemorySize, 204448);

    // 1: fused CSR build (persistent, grid-wide barriers)
    k_build<<<148, 256>>>(ei, ei + Ee);
    // 2: h0 + seq slot 0
    k_in_linear<<<592, 256, 99584>>>(x, W_in, b_in);
    // 3: folded attention matrices
    k_pre<<<16, 256>>>(inW, inb, Wout, bout);
    // 4-6: hops (launch #4 = hop 1 gets profiled)
    const int ib[3] = {0, 1, 2};
    const int ob[3] = {1, 2, 1};
    for (int hop = 0; hop < 3; hop++) {
        k_prop<<<592, 256>>>(ib[hop], ob[hop], sg_W + hop * 4096, sg_b + hop * 64, hop + 1);
    }
    // 7: fused transformer + pooling + classifier
    k_former<<<148, FT, 204448>>>(W1, b1, W2, b2, ln1w, ln1b, ln2w, ln2b, Wcls, bcls, out);
}